// round 6
// baseline (speedup 1.0000x reference)
#include <cuda_runtime.h>
#include <cstdint>

#define EPSF 1e-5f

// ---------------- scratch (device globals; no allocation allowed) ----------
__device__ float    g_x0[20000 * 64];
__device__ float    g_tmp[20000 * 256];
__device__ float    g_bufA[20000 * 256];
__device__ float    g_bufB[20000 * 256];
__device__ float    g_nt[20000 * 128];      // edgeconv node term
__device__ unsigned g_mkey[20000 * 128];    // encoded max accumulator
__device__ int      g_deg[20000];
__device__ float    g_dinv[20000];

// ---------------- helpers ---------------------------------------------------
__device__ __forceinline__ unsigned fenc(float f) {
    unsigned b = __float_as_uint(f);
    return (b & 0x80000000u) ? ~b : (b | 0x80000000u);
}
__device__ __forceinline__ float fdec(unsigned u) {
    return (u & 0x80000000u) ? __uint_as_float(u & 0x7fffffffu)
                             : __uint_as_float(~u);
}

// ---------------- degree / norm --------------------------------------------
__global__ void k_zero_i32(int* p, int n) {
    int i = blockIdx.x * blockDim.x + threadIdx.x;
    if (i < n) p[i] = 0;
}
__global__ void k_zero_u32(unsigned* p, int n) {
    int i = blockIdx.x * blockDim.x + threadIdx.x;
    if (i < n) p[i] = 0u;
}
__global__ void k_count_deg(const int* __restrict__ dst, int E) {
    int i = blockIdx.x * blockDim.x + threadIdx.x;
    if (i < E) atomicAdd(&g_deg[dst[i]], 1);
}
__global__ void k_dinv(int n) {
    int i = blockIdx.x * blockDim.x + threadIdx.x;
    if (i < n) g_dinv[i] = rsqrtf((float)(g_deg[i] + 1));
}

// ---------------- generic tiled GEMM (BM=64, BK=32, 256 thr) ----------------
// C[M,Nout] = op(A)[M,K] @ B[K,Nout]; BNR: A' = relu(A*scale + shift) with
// per-channel BN stats (first-half channels of an EdgeConv layer).
template <int BN, bool BNR>
__global__ __launch_bounds__(256) void k_gemm(
    const float* __restrict__ A, const float* __restrict__ B,
    float* __restrict__ C, int M, int K, int Nout,
    const float* __restrict__ gamma, const float* __restrict__ beta,
    const float* __restrict__ mean, const float* __restrict__ var)
{
    constexpr int TN = BN / 16;
    __shared__ float As[32][68];
    __shared__ float Bs[32][BN];
    __shared__ float s_sc[BNR ? 256 : 4];
    __shared__ float s_sh[BNR ? 256 : 4];

    const int tid = threadIdx.x;
    const int m0 = blockIdx.x * 64;
    const int n0 = blockIdx.y * BN;

    if (BNR) {
        for (int k = tid; k < K; k += 256) {
            float sc = gamma[k] * rsqrtf(var[k] + EPSF);
            s_sc[k] = sc;
            s_sh[k] = beta[k] - mean[k] * sc;
        }
        __syncthreads();
    }

    const int tx = tid & 15, ty = tid >> 4;
    float acc[4][TN];
#pragma unroll
    for (int i = 0; i < 4; i++)
#pragma unroll
        for (int j = 0; j < TN; j++) acc[i][j] = 0.f;

    for (int kt = 0; kt < K; kt += 32) {
#pragma unroll
        for (int it = 0; it < 2; it++) {
            int slot = tid + it * 256;
            int r = slot >> 3, q = slot & 7;
            int m = m0 + r;
            float4 v = make_float4(0.f, 0.f, 0.f, 0.f);
            if (m < M) v = *(const float4*)&A[(size_t)m * K + kt + q * 4];
            if (BNR) {
                int kb = kt + q * 4;
                v.x = fmaxf(v.x * s_sc[kb + 0] + s_sh[kb + 0], 0.f);
                v.y = fmaxf(v.y * s_sc[kb + 1] + s_sh[kb + 1], 0.f);
                v.z = fmaxf(v.z * s_sc[kb + 2] + s_sh[kb + 2], 0.f);
                v.w = fmaxf(v.w * s_sc[kb + 3] + s_sh[kb + 3], 0.f);
            }
            As[q * 4 + 0][r] = v.x;
            As[q * 4 + 1][r] = v.y;
            As[q * 4 + 2][r] = v.z;
            As[q * 4 + 3][r] = v.w;
        }
#pragma unroll
        for (int it = 0; it < BN / 32; it++) {
            int slot = tid + it * 256;
            int row = slot / (BN / 4), c4 = slot % (BN / 4);
            *(float4*)&Bs[row][c4 * 4] =
                *(const float4*)&B[(size_t)(kt + row) * Nout + n0 + c4 * 4];
        }
        __syncthreads();
#pragma unroll
        for (int k = 0; k < 32; k++) {
            float4 a4 = *(const float4*)&As[k][ty * 4];
            float ar[4] = {a4.x, a4.y, a4.z, a4.w};
            float br[TN];
#pragma unroll
            for (int j4 = 0; j4 < TN / 4; j4++) {
                float4 b4 = *(const float4*)&Bs[k][tx * TN + j4 * 4];
                br[j4 * 4 + 0] = b4.x;
                br[j4 * 4 + 1] = b4.y;
                br[j4 * 4 + 2] = b4.z;
                br[j4 * 4 + 3] = b4.w;
            }
#pragma unroll
            for (int i = 0; i < 4; i++)
#pragma unroll
                for (int j = 0; j < TN; j++)
                    acc[i][j] = fmaf(ar[i], br[j], acc[i][j]);
        }
        __syncthreads();
    }
#pragma unroll
    for (int i = 0; i < 4; i++) {
        int m = m0 + ty * 4 + i;
        if (m < M) {
#pragma unroll
            for (int j4 = 0; j4 < TN / 4; j4++) {
                float4 o = make_float4(acc[i][j4 * 4 + 0], acc[i][j4 * 4 + 1],
                                       acc[i][j4 * 4 + 2], acc[i][j4 * 4 + 3]);
                *(float4*)&C[(size_t)m * Nout + n0 + tx * TN + j4 * 4] = o;
            }
        }
    }
}

// ---------------- input projection with per-row weight select ---------------
// rows with m%4==0 use (Wm,bm), others (Wc,bc). K=512, Nout=64.
__global__ __launch_bounds__(256) void k_proj(
    const float* __restrict__ x, const float* __restrict__ Wm,
    const float* __restrict__ bm, const float* __restrict__ Wc,
    const float* __restrict__ bc, float* __restrict__ out, int M)
{
    __shared__ float As[32][68];
    __shared__ float Bm_s[32][64];
    __shared__ float Bc_s[32][64];
    const int tid = threadIdx.x;
    const int m0 = blockIdx.x * 64;
    const int tx = tid & 15, ty = tid >> 4;
    float acc[4][4] = {};

    for (int kt = 0; kt < 512; kt += 32) {
#pragma unroll
        for (int it = 0; it < 2; it++) {
            int slot = tid + it * 256;
            int r = slot >> 3, q = slot & 7;
            int m = m0 + r;
            float4 v = make_float4(0.f, 0.f, 0.f, 0.f);
            if (m < M) v = *(const float4*)&x[(size_t)m * 512 + kt + q * 4];
            As[q * 4 + 0][r] = v.x;
            As[q * 4 + 1][r] = v.y;
            As[q * 4 + 2][r] = v.z;
            As[q * 4 + 3][r] = v.w;
        }
#pragma unroll
        for (int it = 0; it < 2; it++) {
            int slot = tid + it * 256;
            int row = slot >> 4, c4 = slot & 15;
            *(float4*)&Bm_s[row][c4 * 4] =
                *(const float4*)&Wm[(size_t)(kt + row) * 64 + c4 * 4];
            *(float4*)&Bc_s[row][c4 * 4] =
                *(const float4*)&Wc[(size_t)(kt + row) * 64 + c4 * 4];
        }
        __syncthreads();
#pragma unroll
        for (int k = 0; k < 32; k++) {
            float4 a4 = *(const float4*)&As[k][ty * 4];
            float4 bm4 = *(const float4*)&Bm_s[k][tx * 4];
            float4 bc4 = *(const float4*)&Bc_s[k][tx * 4];
            float bmr[4] = {bm4.x, bm4.y, bm4.z, bm4.w};
            float bcr[4] = {bc4.x, bc4.y, bc4.z, bc4.w};
            float ar[4] = {a4.x, a4.y, a4.z, a4.w};
#pragma unroll
            for (int j = 0; j < 4; j++) acc[0][j] = fmaf(ar[0], bmr[j], acc[0][j]);
#pragma unroll
            for (int i = 1; i < 4; i++)
#pragma unroll
                for (int j = 0; j < 4; j++) acc[i][j] = fmaf(ar[i], bcr[j], acc[i][j]);
        }
        __syncthreads();
    }
#pragma unroll
    for (int i = 0; i < 4; i++) {
        int m = m0 + ty * 4 + i;
        if (m < M) {
            const float* bias = (i == 0) ? bm : bc;
#pragma unroll
            for (int j = 0; j < 4; j++)
                out[(size_t)m * 64 + tx * 4 + j] = acc[i][j] + bias[tx * 4 + j];
        }
    }
}

// ---------------- GCN aggregation -------------------------------------------
// out init: bias + self-loop term
__global__ void k_gcn_init(const float* __restrict__ tmp,
                           const float* __restrict__ bias,
                           float* __restrict__ out, int n, int Wd)
{
    int idx = blockIdx.x * blockDim.x + threadIdx.x;
    if (idx < n * Wd) {
        int i = idx / Wd;
        int c = idx - i * Wd;
        float dv = g_dinv[i];
        out[idx] = bias[c] + tmp[idx] * dv * dv;
    }
}
// one warp per edge: out[dst] += tmp[src] * dinv[src]*dinv[dst]
__global__ void k_gcn_edge(const float* __restrict__ tmp,
                           const int* __restrict__ src,
                           const int* __restrict__ dst,
                           float* __restrict__ out, int E, int W4)
{
    int g = blockIdx.x * blockDim.x + threadIdx.x;
    int e = g >> 5, lane = g & 31;
    if (e >= E) return;
    int s = src[e], d = dst[e];
    float coef = g_dinv[s] * g_dinv[d];
    const float4* ts = (const float4*)(tmp + (size_t)s * W4 * 4);
    float4* od = (float4*)(out + (size_t)d * W4 * 4);
    for (int j = lane; j < W4; j += 32) {
        float4 v = ts[j];
        v.x *= coef; v.y *= coef; v.z *= coef; v.w *= coef;
        asm volatile("red.global.add.v4.f32 [%0], {%1,%2,%3,%4};"
                     :: "l"(od + j), "f"(v.x), "f"(v.y), "f"(v.z), "f"(v.w)
                     : "memory");
    }
}

// ---------------- EdgeConv edge term ----------------------------------------
// b_e = relu( (x[src]-x[dst]) * sc2 + sh2 ) @ W_bot ; atomicMax into mkey[dst]
template <int C>
__global__ __launch_bounds__(256) void k_edge_term(
    const float* __restrict__ xf, const int* __restrict__ src,
    const int* __restrict__ dst,
    const float* __restrict__ gamma, const float* __restrict__ beta,
    const float* __restrict__ mean, const float* __restrict__ var,
    const float* __restrict__ W,  // full [2C,128]; rows C..2C-1 used
    unsigned* __restrict__ mkey, int E)
{
    __shared__ float As[32][68];
    __shared__ float Bs[32][128];
    __shared__ float s_sc[C], s_sh[C];
    __shared__ int s_src[64], s_dst[64];
    const int tid = threadIdx.x;

    for (int k = tid; k < C; k += 256) {
        float sc = gamma[C + k] * rsqrtf(var[C + k] + EPSF);
        s_sc[k] = sc;
        s_sh[k] = beta[C + k] - mean[C + k] * sc;
    }
    const int e0 = blockIdx.x * 64;
    if (tid < 64) {
        int e = e0 + tid;
        s_src[tid] = (e < E) ? src[e] : 0;
        s_dst[tid] = (e < E) ? dst[e] : 0;
    }
    __syncthreads();

    const int tx = tid & 15, ty = tid >> 4;
    float acc[4][8] = {};
    const float* Wb = W + (size_t)C * 128;

    for (int kt = 0; kt < C; kt += 32) {
#pragma unroll
        for (int it = 0; it < 2; it++) {
            int slot = tid + it * 256;
            int r = slot >> 3, q = slot & 7;
            const float4 a = *(const float4*)&xf[(size_t)s_src[r] * C + kt + q * 4];
            const float4 b = *(const float4*)&xf[(size_t)s_dst[r] * C + kt + q * 4];
            int kb = kt + q * 4;
            As[q * 4 + 0][r] = fmaxf((a.x - b.x) * s_sc[kb + 0] + s_sh[kb + 0], 0.f);
            As[q * 4 + 1][r] = fmaxf((a.y - b.y) * s_sc[kb + 1] + s_sh[kb + 1], 0.f);
            As[q * 4 + 2][r] = fmaxf((a.z - b.z) * s_sc[kb + 2] + s_sh[kb + 2], 0.f);
            As[q * 4 + 3][r] = fmaxf((a.w - b.w) * s_sc[kb + 3] + s_sh[kb + 3], 0.f);
        }
#pragma unroll
        for (int it = 0; it < 4; it++) {
            int slot = tid + it * 256;
            int row = slot >> 5, c4 = slot & 31;
            *(float4*)&Bs[row][c4 * 4] =
                *(const float4*)&Wb[(size_t)(kt + row) * 128 + c4 * 4];
        }
        __syncthreads();
#pragma unroll
        for (int k = 0; k < 32; k++) {
            float4 a4 = *(const float4*)&As[k][ty * 4];
            float ar[4] = {a4.x, a4.y, a4.z, a4.w};
            float4 b0 = *(const float4*)&Bs[k][tx * 8];
            float4 b1 = *(const float4*)&Bs[k][tx * 8 + 4];
            float br[8] = {b0.x, b0.y, b0.z, b0.w, b1.x, b1.y, b1.z, b1.w};
#pragma unroll
            for (int i = 0; i < 4; i++)
#pragma unroll
                for (int j = 0; j < 8; j++)
                    acc[i][j] = fmaf(ar[i], br[j], acc[i][j]);
        }
        __syncthreads();
    }
#pragma unroll
    for (int i = 0; i < 4; i++) {
        int el = ty * 4 + i;
        int e = e0 + el;
        if (e < E) {
            unsigned* mp = mkey + (size_t)s_dst[el] * 128 + tx * 8;
#pragma unroll
            for (int j = 0; j < 8; j++) atomicMax(mp + j, fenc(acc[i][j]));
        }
    }
}

// h[i] = deg>0 ? node_term + decode(max) : 0
__global__ void k_ec_final(const float* __restrict__ a,
                           const unsigned* __restrict__ mk,
                           float* __restrict__ h, int n)
{
    int idx = blockIdx.x * blockDim.x + threadIdx.x;
    if (idx < n * 128) {
        int i = idx >> 7;
        h[idx] = (g_deg[i] > 0) ? (a[idx] + fdec(mk[idx])) : 0.f;
    }
}

// ---------------- final FC ---------------------------------------------------
__global__ void k_final(const float* __restrict__ h, const float* __restrict__ Wfc,
                        const float* __restrict__ bfc, float* __restrict__ out, int n)
{
    int g = blockIdx.x * blockDim.x + threadIdx.x;
    int w = g >> 5, lane = g & 31;
    if (w >= n) return;
    float4 a = *(const float4*)&h[(size_t)w * 128 + lane * 4];
    float4 ww = *(const float4*)&Wfc[lane * 4];
    float s = a.x * ww.x + a.y * ww.y + a.z * ww.z + a.w * ww.w;
#pragma unroll
    for (int o = 16; o > 0; o >>= 1) s += __shfl_xor_sync(0xffffffffu, s, o);
    if (lane == 0) out[w] = s + bfc[0];
}

// ---------------- launch ------------------------------------------------------
extern "C" void kernel_launch(void* const* d_in, const int* in_sizes, int n_in,
                              void* d_out, int out_size)
{
    const float* x   = (const float*)d_in[0];
    const int*   ei  = (const int*)d_in[1];
    const float* Wm  = (const float*)d_in[2];
    const float* bm  = (const float*)d_in[3];
    const float* Wc  = (const float*)d_in[4];
    const float* bc  = (const float*)d_in[5];
    const float* Wg1 = (const float*)d_in[6];
    const float* bg1 = (const float*)d_in[7];
    const float* Wg2 = (const float*)d_in[8];
    const float* bg2 = (const float*)d_in[9];
    const float* Wg3 = (const float*)d_in[10];
    const float* bg3 = (const float*)d_in[11];
    const float* e1g = (const float*)d_in[12];
    const float* e1b = (const float*)d_in[13];
    const float* e1m = (const float*)d_in[14];
    const float* e1v = (const float*)d_in[15];
    const float* e1W = (const float*)d_in[16];
    const float* e2g = (const float*)d_in[17];
    const float* e2b = (const float*)d_in[18];
    const float* e2m = (const float*)d_in[19];
    const float* e2v = (const float*)d_in[20];
    const float* e2W = (const float*)d_in[21];
    const float* e3g = (const float*)d_in[22];
    const float* e3b = (const float*)d_in[23];
    const float* e3m = (const float*)d_in[24];
    const float* e3v = (const float*)d_in[25];
    const float* e3W = (const float*)d_in[26];
    const float* Wfc = (const float*)d_in[27];
    const float* bfc = (const float*)d_in[28];
    float* out = (float*)d_out;

    const int n = in_sizes[0] / 512;
    const int E = in_sizes[1] / 2;
    const int* src = ei;
    const int* dst = ei + E;

    float *p_x0, *p_tmp, *p_bufA, *p_bufB, *p_nt, *p_dinv;
    unsigned* p_mkey;
    int* p_deg;
    cudaGetSymbolAddress((void**)&p_x0, g_x0);
    cudaGetSymbolAddress((void**)&p_tmp, g_tmp);
    cudaGetSymbolAddress((void**)&p_bufA, g_bufA);
    cudaGetSymbolAddress((void**)&p_bufB, g_bufB);
    cudaGetSymbolAddress((void**)&p_nt, g_nt);
    cudaGetSymbolAddress((void**)&p_mkey, g_mkey);
    cudaGetSymbolAddress((void**)&p_deg, g_deg);
    cudaGetSymbolAddress((void**)&p_dinv, g_dinv);

    const int mb = (n + 63) / 64;
    const int THR = 256;
    auto blks = [&](int work) { return (work + THR - 1) / THR; };

    // degrees + normalization
    k_zero_i32<<<blks(n), THR>>>(p_deg, n);
    k_count_deg<<<blks(E), THR>>>(dst, E);
    k_dinv<<<blks(n), THR>>>(n);

    // input projection (row-select Wm/Wc)
    k_proj<<<mb, THR>>>(x, Wm, bm, Wc, bc, p_x0, n);

    // GCN 1: 64 -> 128
    k_gemm<128, false><<<dim3(mb, 1), THR>>>(p_x0, Wg1, p_tmp, n, 64, 128,
                                             nullptr, nullptr, nullptr, nullptr);
    k_gcn_init<<<blks(n * 128), THR>>>(p_tmp, bg1, p_bufA, n, 128);
    k_gcn_edge<<<(E + 7) / 8, THR>>>(p_tmp, src, dst, p_bufA, E, 32);

    // GCN 2: 128 -> 128
    k_gemm<128, false><<<dim3(mb, 1), THR>>>(p_bufA, Wg2, p_tmp, n, 128, 128,
                                             nullptr, nullptr, nullptr, nullptr);
    k_gcn_init<<<blks(n * 128), THR>>>(p_tmp, bg2, p_bufB, n, 128);
    k_gcn_edge<<<(E + 7) / 8, THR>>>(p_tmp, src, dst, p_bufB, E, 32);

    // GCN 3: 128 -> 256
    k_gemm<128, false><<<dim3(mb, 2), THR>>>(p_bufB, Wg3, p_tmp, n, 128, 256,
                                             nullptr, nullptr, nullptr, nullptr);
    k_gcn_init<<<blks(n * 256), THR>>>(p_tmp, bg3, p_bufA, n, 256);
    k_gcn_edge<<<(E + 7) / 8, THR>>>(p_tmp, src, dst, p_bufA, E, 64);

    // EdgeConv 1: C=256 -> 128   (in: p_bufA, out: p_bufB)
    k_gemm<128, true><<<dim3(mb, 1), THR>>>(p_bufA, e1W, p_nt, n, 256, 128,
                                            e1g, e1b, e1m, e1v);
    k_zero_u32<<<blks(n * 128), THR>>>(p_mkey, n * 128);
    k_edge_term<256><<<(E + 63) / 64, THR>>>(p_bufA, src, dst, e1g, e1b, e1m,
                                             e1v, e1W, p_mkey, E);
    k_ec_final<<<blks(n * 128), THR>>>(p_nt, p_mkey, p_bufB, n);

    // EdgeConv 2: C=128 -> 128   (in: p_bufB, out: p_tmp)
    k_gemm<128, true><<<dim3(mb, 1), THR>>>(p_bufB, e2W, p_nt, n, 128, 128,
                                            e2g, e2b, e2m, e2v);
    k_zero_u32<<<blks(n * 128), THR>>>(p_mkey, n * 128);
    k_edge_term<128><<<(E + 63) / 64, THR>>>(p_bufB, src, dst, e2g, e2b, e2m,
                                             e2v, e2W, p_mkey, E);
    k_ec_final<<<blks(n * 128), THR>>>(p_nt, p_mkey, p_tmp, n);

    // EdgeConv 3: C=128 -> 128   (in: p_tmp, out: p_bufA)
    k_gemm<128, true><<<dim3(mb, 1), THR>>>(p_tmp, e3W, p_nt, n, 128, 128,
                                            e3g, e3b, e3m, e3v);
    k_zero_u32<<<blks(n * 128), THR>>>(p_mkey, n * 128);
    k_edge_term<128><<<(E + 63) / 64, THR>>>(p_tmp, src, dst, e3g, e3b, e3m,
                                             e3v, e3W, p_mkey, E);
    k_ec_final<<<blks(n * 128), THR>>>(p_nt, p_mkey, p_bufA, n);

    // final FC: [N,128] @ [128,1] + b
    k_final<<<blks(n * 32), THR>>>(p_bufA, Wfc, bfc, out, n);
}

// round 9
// speedup vs baseline: 1.9239x; 1.9239x over previous
#include <cuda_runtime.h>
#include <cuda_bf16.h>
#include <cstdint>

#define EPSF 1e-5f

// ---------------- scratch ----------------------------------------------------
__device__ float    g_x0[20000 * 64];
__device__ float    g_tmp[20000 * 256];
__device__ float    g_bufA[20000 * 256];
__device__ float    g_bufB[20000 * 256];
__device__ float    g_nt[20000 * 128];
__device__ unsigned g_mkey[20000 * 128];
__device__ int      g_deg[20000];
__device__ float    g_dinv[20000];
// pair-packed bf16 weights: [chunk k/32][n:128][kp:16] u32 = (bf16 k, bf16 k+1)
__device__ uint32_t g_wp0h[16384], g_wp0l[16384];   // e1 (C=256)
__device__ uint32_t g_wp1h[8192],  g_wp1l[8192];    // e2 (C=128)
__device__ uint32_t g_wp2h[8192],  g_wp2l[8192];    // e3 (C=128)
__device__ float g_scl[512], g_shl[512];

// ---------------- helpers ----------------------------------------------------
__device__ __forceinline__ unsigned fenc(float f) {
    unsigned b = __float_as_uint(f);
    return (b & 0x80000000u) ? ~b : (b | 0x80000000u);
}
__device__ __forceinline__ float fdec(unsigned u) {
    return (u & 0x80000000u) ? __uint_as_float(u & 0x7fffffffu) : __uint_as_float(~u);
}
__device__ __forceinline__ unsigned packbf(__nv_bfloat16 a, __nv_bfloat16 b) {
    return ((unsigned)__bfloat16_as_ushort(b) << 16) | (unsigned)__bfloat16_as_ushort(a);
}
// warp mma: D(16x8,f32) += A(16x16,bf16) * B(16x8,bf16)
__device__ __forceinline__ void mma_bf16(float* c, const uint32_t* a, uint32_t b0, uint32_t b1) {
    asm volatile(
        "mma.sync.aligned.m16n8k16.row.col.f32.bf16.bf16.f32 "
        "{%0,%1,%2,%3}, {%4,%5,%6,%7}, {%8,%9}, {%0,%1,%2,%3};"
        : "+f"(c[0]), "+f"(c[1]), "+f"(c[2]), "+f"(c[3])
        : "r"(a[0]), "r"(a[1]), "r"(a[2]), "r"(a[3]), "r"(b0), "r"(b1));
}

// ---------------- tiny kernels -----------------------------------------------
__global__ void k_zero_i32(int* p, int n) {
    int i = blockIdx.x * blockDim.x + threadIdx.x;
    if (i < n) p[i] = 0;
}
__global__ void k_zero_u32(unsigned* p, int n) {
    int i = blockIdx.x * blockDim.x + threadIdx.x;
    if (i < n) p[i] = 0u;
}
__global__ void k_count_deg(const int* __restrict__ dst, int E) {
    int i = blockIdx.x * blockDim.x + threadIdx.x;
    if (i < E) atomicAdd(&g_deg[dst[i]], 1);
}
__global__ void k_dinv(int n) {
    int i = blockIdx.x * blockDim.x + threadIdx.x;
    if (i < n) g_dinv[i] = rsqrtf((float)(g_deg[i] + 1));
}

// ---------------- weight prep: bottom-half rows, bf16 hi/lo, pair-packed -----
__global__ void k_prep_w(const float* __restrict__ W,
                         const float* __restrict__ gamma, const float* __restrict__ beta,
                         const float* __restrict__ mean, const float* __restrict__ var,
                         int C, uint32_t* __restrict__ bh, uint32_t* __restrict__ bl,
                         float* __restrict__ sc, float* __restrict__ sh)
{
    int idx = blockIdx.x * blockDim.x + threadIdx.x;
    if (idx >= (C / 2) * 128) return;
    int n = idx & 127, kp = idx >> 7;
    int k0 = kp * 2, k1 = k0 + 1;
    float w0 = W[(size_t)(C + k0) * 128 + n];
    float w1 = W[(size_t)(C + k1) * 128 + n];
    __nv_bfloat16 h0 = __float2bfloat16_rn(w0);
    __nv_bfloat16 h1 = __float2bfloat16_rn(w1);
    __nv_bfloat16 l0 = __float2bfloat16_rn(w0 - __bfloat162float(h0));
    __nv_bfloat16 l1 = __float2bfloat16_rn(w1 - __bfloat162float(h1));
    int chunk = kp >> 4, kpin = kp & 15;
    int o = (chunk * 128 + n) * 16 + kpin;
    bh[o] = packbf(h0, h1);
    bl[o] = packbf(l0, l1);
    if (n == 0) {
        float s0 = gamma[C + k0] * rsqrtf(var[C + k0] + EPSF);
        float s1 = gamma[C + k1] * rsqrtf(var[C + k1] + EPSF);
        sc[k0] = s0; sh[k0] = beta[C + k0] - mean[C + k0] * s0;
        sc[k1] = s1; sh[k1] = beta[C + k1] - mean[C + k1] * s1;
    }
}

// ---------------- tiled scalar GEMM (BM=64, BK=32) ---------------------------
template <int BN, bool BNR>
__global__ __launch_bounds__(256) void k_gemm(
    const float* __restrict__ A, const float* __restrict__ B,
    float* __restrict__ C, int M, int K, int Nout,
    const float* __restrict__ gamma, const float* __restrict__ beta,
    const float* __restrict__ mean, const float* __restrict__ var,
    const float* __restrict__ bias)
{
    constexpr int TN = BN / 16;
    __shared__ float As[32][68];
    __shared__ float Bs[32][BN];
    __shared__ float s_sc[BNR ? 256 : 4];
    __shared__ float s_sh[BNR ? 256 : 4];

    const int tid = threadIdx.x;
    const int m0 = blockIdx.x * 64;
    const int n0 = blockIdx.y * BN;

    if (BNR) {
        for (int k = tid; k < K; k += 256) {
            float sc = gamma[k] * rsqrtf(var[k] + EPSF);
            s_sc[k] = sc;
            s_sh[k] = beta[k] - mean[k] * sc;
        }
        __syncthreads();
    }

    const int tx = tid & 15, ty = tid >> 4;
    float acc[4][TN];
#pragma unroll
    for (int i = 0; i < 4; i++)
#pragma unroll
        for (int j = 0; j < TN; j++) acc[i][j] = 0.f;

    for (int kt = 0; kt < K; kt += 32) {
#pragma unroll
        for (int it = 0; it < 2; it++) {
            int slot = tid + it * 256;
            int r = slot >> 3, q = slot & 7;
            int m = m0 + r;
            float4 v = make_float4(0.f, 0.f, 0.f, 0.f);
            if (m < M) v = *(const float4*)&A[(size_t)m * K + kt + q * 4];
            if (BNR) {
                int kb = kt + q * 4;
                v.x = fmaxf(v.x * s_sc[kb + 0] + s_sh[kb + 0], 0.f);
                v.y = fmaxf(v.y * s_sc[kb + 1] + s_sh[kb + 1], 0.f);
                v.z = fmaxf(v.z * s_sc[kb + 2] + s_sh[kb + 2], 0.f);
                v.w = fmaxf(v.w * s_sc[kb + 3] + s_sh[kb + 3], 0.f);
            }
            As[q * 4 + 0][r] = v.x;
            As[q * 4 + 1][r] = v.y;
            As[q * 4 + 2][r] = v.z;
            As[q * 4 + 3][r] = v.w;
        }
#pragma unroll
        for (int it = 0; it < BN / 32; it++) {
            int slot = tid + it * 256;
            int row = slot / (BN / 4), c4 = slot % (BN / 4);
            *(float4*)&Bs[row][c4 * 4] =
                *(const float4*)&B[(size_t)(kt + row) * Nout + n0 + c4 * 4];
        }
        __syncthreads();
#pragma unroll
        for (int k = 0; k < 32; k++) {
            float4 a4 = *(const float4*)&As[k][ty * 4];
            float ar[4] = {a4.x, a4.y, a4.z, a4.w};
            float br[TN];
#pragma unroll
            for (int j4 = 0; j4 < TN / 4; j4++) {
                float4 b4 = *(const float4*)&Bs[k][tx * TN + j4 * 4];
                br[j4 * 4 + 0] = b4.x;
                br[j4 * 4 + 1] = b4.y;
                br[j4 * 4 + 2] = b4.z;
                br[j4 * 4 + 3] = b4.w;
            }
#pragma unroll
            for (int i = 0; i < 4; i++)
#pragma unroll
                for (int j = 0; j < TN; j++)
                    acc[i][j] = fmaf(ar[i], br[j], acc[i][j]);
        }
        __syncthreads();
    }
#pragma unroll
    for (int i = 0; i < 4; i++) {
        int m = m0 + ty * 4 + i;
        if (m < M) {
#pragma unroll
            for (int j4 = 0; j4 < TN / 4; j4++) {
                int c = n0 + tx * TN + j4 * 4;
                float4 o = make_float4(acc[i][j4 * 4 + 0], acc[i][j4 * 4 + 1],
                                       acc[i][j4 * 4 + 2], acc[i][j4 * 4 + 3]);
                if (bias) {
                    o.x += bias[c + 0]; o.y += bias[c + 1];
                    o.z += bias[c + 2]; o.w += bias[c + 3];
                }
                *(float4*)&C[(size_t)m * Nout + c] = o;
            }
        }
    }
}

// ---------------- input projection (row-select Wm/Wc) ------------------------
__global__ __launch_bounds__(256) void k_proj(
    const float* __restrict__ x, const float* __restrict__ Wm,
    const float* __restrict__ bm, const float* __restrict__ Wc,
    const float* __restrict__ bc, float* __restrict__ out, int M)
{
    __shared__ float As[32][68];
    __shared__ float Bm_s[32][64];
    __shared__ float Bc_s[32][64];
    const int tid = threadIdx.x;
    const int m0 = blockIdx.x * 64;
    const int tx = tid & 15, ty = tid >> 4;
    float acc[4][4] = {};

    for (int kt = 0; kt < 512; kt += 32) {
#pragma unroll
        for (int it = 0; it < 2; it++) {
            int slot = tid + it * 256;
            int r = slot >> 3, q = slot & 7;
            int m = m0 + r;
            float4 v = make_float4(0.f, 0.f, 0.f, 0.f);
            if (m < M) v = *(const float4*)&x[(size_t)m * 512 + kt + q * 4];
            As[q * 4 + 0][r] = v.x;
            As[q * 4 + 1][r] = v.y;
            As[q * 4 + 2][r] = v.z;
            As[q * 4 + 3][r] = v.w;
        }
#pragma unroll
        for (int it = 0; it < 2; it++) {
            int slot = tid + it * 256;
            int row = slot >> 4, c4 = slot & 15;
            *(float4*)&Bm_s[row][c4 * 4] = *(const float4*)&Wm[(size_t)(kt + row) * 64 + c4 * 4];
            *(float4*)&Bc_s[row][c4 * 4] = *(const float4*)&Wc[(size_t)(kt + row) * 64 + c4 * 4];
        }
        __syncthreads();
#pragma unroll
        for (int k = 0; k < 32; k++) {
            float4 a4 = *(const float4*)&As[k][ty * 4];
            float4 bm4 = *(const float4*)&Bm_s[k][tx * 4];
            float4 bc4 = *(const float4*)&Bc_s[k][tx * 4];
            float bmr[4] = {bm4.x, bm4.y, bm4.z, bm4.w};
            float bcr[4] = {bc4.x, bc4.y, bc4.z, bc4.w};
            float ar[4] = {a4.x, a4.y, a4.z, a4.w};
#pragma unroll
            for (int j = 0; j < 4; j++) acc[0][j] = fmaf(ar[0], bmr[j], acc[0][j]);
#pragma unroll
            for (int i = 1; i < 4; i++)
#pragma unroll
                for (int j = 0; j < 4; j++) acc[i][j] = fmaf(ar[i], bcr[j], acc[i][j]);
        }
        __syncthreads();
    }
#pragma unroll
    for (int i = 0; i < 4; i++) {
        int m = m0 + ty * 4 + i;
        if (m < M) {
            const float* bias = (i == 0) ? bm : bc;
#pragma unroll
            for (int j = 0; j < 4; j++)
                out[(size_t)m * 64 + tx * 4 + j] = acc[i][j] + bias[tx * 4 + j];
        }
    }
}

// ---------------- GCN aggregation (aggregate-first) --------------------------
__global__ void k_gcn_init(const float* __restrict__ in, float* __restrict__ out,
                           int n, int Wd)
{
    int idx = blockIdx.x * blockDim.x + threadIdx.x;
    if (idx < n * Wd) {
        int i = idx / Wd;
        float dv = g_dinv[i];
        out[idx] = in[idx] * dv * dv;
    }
}
__global__ void k_gcn_edge(const float* __restrict__ xin,
                           const int* __restrict__ src, const int* __restrict__ dst,
                           float* __restrict__ out, int E, int W4)
{
    int g = blockIdx.x * blockDim.x + threadIdx.x;
    int e = g >> 5, lane = g & 31;
    if (e >= E) return;
    int s = src[e], d = dst[e];
    float coef = g_dinv[s] * g_dinv[d];
    const float4* ts = (const float4*)(xin + (size_t)s * W4 * 4);
    float4* od = (float4*)(out + (size_t)d * W4 * 4);
    for (int j = lane; j < W4; j += 32) {
        float4 v = ts[j];
        v.x *= coef; v.y *= coef; v.z *= coef; v.w *= coef;
        asm volatile("red.global.add.v4.f32 [%0], {%1,%2,%3,%4};"
                     :: "l"(od + j), "f"(v.x), "f"(v.y), "f"(v.z), "f"(v.w) : "memory");
    }
}

// ---------------- EdgeConv edge term: warp mma.sync bf16 hi/lo x3 ------------
// Block: 128 edges x 128 outs, 8 warps in 4(M) x 2(N) grid, each warp 32x64.
// b_e = relu(bn2(x[src]-x[dst])) @ W_bot, scattered via atomicMax(mkey[dst]).
template <int C>
__global__ __launch_bounds__(256, 2) void k_ec_mma(
    const float* __restrict__ xf, const int* __restrict__ src, const int* __restrict__ dst,
    const uint32_t* __restrict__ wph, const uint32_t* __restrict__ wpl,
    const float* __restrict__ scv, const float* __restrict__ shv,
    unsigned* __restrict__ mkey, int E)
{
    __shared__ uint32_t As_h[128 * 20], As_l[128 * 20];   // [edge row][kp], stride 20
    __shared__ uint32_t Bs_h[128 * 20], Bs_l[128 * 20];   // [n][kp], stride 20
    __shared__ int s_srcsh[128], s_dst[128];

    const int tid = threadIdx.x;
    const int w = tid >> 5, lane = tid & 31;
    const int wm = w & 3, wn = w >> 2;
    const int gr = lane >> 2, gc2 = lane & 3;
    const int e0 = blockIdx.x * 128;

    if (tid < 128) {
        int e = e0 + tid;
        s_srcsh[tid] = (e < E) ? src[e] : 0;
        s_dst[tid]   = (e < E) ? dst[e] : 0;
    }
    __syncthreads();

    // staging role: 2 threads per edge row, each covers 16 k of the 32-chunk
    const int r = tid >> 1, hh = tid & 1;
    const float* xs0 = xf + (size_t)s_srcsh[r] * C + hh * 16;
    const float* xd0 = xf + (size_t)s_dst[r] * C + hh * 16;

    float acc[2][8][4];
#pragma unroll
    for (int a = 0; a < 2; a++)
#pragma unroll
        for (int b = 0; b < 8; b++)
#pragma unroll
            for (int c = 0; c < 4; c++) acc[a][b][c] = 0.f;

#pragma unroll 1
    for (int kc = 0; kc < C / 32; kc++) {
        // stage B chunk (pair-packed in gmem -> stride-20 smem)
        const uint32_t* gh = wph + kc * 2048;
        const uint32_t* gl = wpl + kc * 2048;
#pragma unroll
        for (int i = tid; i < 2048; i += 256) {
            int nn = i >> 4, kp = i & 15;
            Bs_h[nn * 20 + kp] = gh[i];
            Bs_l[nn * 20 + kp] = gl[i];
        }
        // stage A: gather + BN + ReLU + hi/lo split
        {
            const float4* xs = (const float4*)(xs0 + kc * 32);
            const float4* xd = (const float4*)(xd0 + kc * 32);
            const float4* s4 = (const float4*)(scv + kc * 32 + hh * 16);
            const float4* t4 = (const float4*)(shv + kc * 32 + hh * 16);
            uint32_t* ph = &As_h[r * 20 + hh * 8];
            uint32_t* pl = &As_l[r * 20 + hh * 8];
#pragma unroll
            for (int j = 0; j < 4; j++) {
                float4 a = xs[j], d = xd[j], s = s4[j], t = t4[j];
                float u0 = fmaxf(fmaf(a.x - d.x, s.x, t.x), 0.f);
                float u1 = fmaxf(fmaf(a.y - d.y, s.y, t.y), 0.f);
                float u2 = fmaxf(fmaf(a.z - d.z, s.z, t.z), 0.f);
                float u3 = fmaxf(fmaf(a.w - d.w, s.w, t.w), 0.f);
                __nv_bfloat16 h0 = __float2bfloat16_rn(u0);
                __nv_bfloat16 h1 = __float2bfloat16_rn(u1);
                __nv_bfloat16 h2 = __float2bfloat16_rn(u2);
                __nv_bfloat16 h3 = __float2bfloat16_rn(u3);
                ph[2 * j + 0] = packbf(h0, h1);
                ph[2 * j + 1] = packbf(h2, h3);
                pl[2 * j + 0] = packbf(__float2bfloat16_rn(u0 - __bfloat162float(h0)),
                                       __float2bfloat16_rn(u1 - __bfloat162float(h1)));
                pl[2 * j + 1] = packbf(__float2bfloat16_rn(u2 - __bfloat162float(h2)),
                                       __float2bfloat16_rn(u3 - __bfloat162float(h3)));
            }
        }
        __syncthreads();
        // mma over the 32-k chunk: two k16 steps
#pragma unroll
        for (int kk = 0; kk < 2; kk++) {
            uint32_t ah[2][4], al[2][4];
#pragma unroll
            for (int mf = 0; mf < 2; mf++) {
                int r0 = (wm * 32 + mf * 16 + gr) * 20 + kk * 8 + gc2;
                ah[mf][0] = As_h[r0];
                ah[mf][1] = As_h[r0 + 160];   // +8 rows
                ah[mf][2] = As_h[r0 + 4];     // +8 k
                ah[mf][3] = As_h[r0 + 164];
                al[mf][0] = As_l[r0];
                al[mf][1] = As_l[r0 + 160];
                al[mf][2] = As_l[r0 + 4];
                al[mf][3] = As_l[r0 + 164];
            }
#pragma unroll
            for (int nf = 0; nf < 8; nf++) {
                int nb = (wn * 64 + nf * 8 + gr) * 20 + kk * 8 + gc2;
                uint32_t b0h = Bs_h[nb], b1h = Bs_h[nb + 4];
                uint32_t b0l = Bs_l[nb], b1l = Bs_l[nb + 4];
#pragma unroll
                for (int mf = 0; mf < 2; mf++) {
                    mma_bf16(acc[mf][nf], ah[mf], b0h, b1h);
                    mma_bf16(acc[mf][nf], ah[mf], b0l, b1l);
                    mma_bf16(acc[mf][nf], al[mf], b0h, b1h);
                }
            }
        }
        __syncthreads();
    }

    // epilogue: scatter D frags via encoded atomicMax
#pragma unroll
    for (int mf = 0; mf < 2; mf++) {
        int er0 = wm * 32 + mf * 16 + gr;
        int er1 = er0 + 8;
        bool v0 = (e0 + er0 < E), v1 = (e0 + er1 < E);
        unsigned* base0 = mkey + (size_t)s_dst[er0] * 128;
        unsigned* base1 = mkey + (size_t)s_dst[er1] * 128;
#pragma unroll
        for (int nf = 0; nf < 8; nf++) {
            int col = wn * 64 + nf * 8 + gc2 * 2;
            if (v0) {
                atomicMax(base0 + col,     fenc(acc[mf][nf][0]));
                atomicMax(base0 + col + 1, fenc(acc[mf][nf][1]));
            }
            if (v1) {
                atomicMax(base1 + col,     fenc(acc[mf][nf][2]));
                atomicMax(base1 + col + 1, fenc(acc[mf][nf][3]));
            }
        }
    }
}

__global__ void k_ec_final(const float* __restrict__ a, const unsigned* __restrict__ mk,
                           float* __restrict__ h, int n)
{
    int idx = blockIdx.x * blockDim.x + threadIdx.x;
    if (idx < n * 128) {
        int i = idx >> 7;
        h[idx] = (g_deg[i] > 0) ? (a[idx] + fdec(mk[idx])) : 0.f;
    }
}

__global__ void k_final(const float* __restrict__ h, const float* __restrict__ Wfc,
                        const float* __restrict__ bfc, float* __restrict__ out, int n)
{
    int g = blockIdx.x * blockDim.x + threadIdx.x;
    int w = g >> 5, lane = g & 31;
    if (w >= n) return;
    float4 a = *(const float4*)&h[(size_t)w * 128 + lane * 4];
    float4 ww = *(const float4*)&Wfc[lane * 4];
    float s = a.x * ww.x + a.y * ww.y + a.z * ww.z + a.w * ww.w;
#pragma unroll
    for (int o = 16; o > 0; o >>= 1) s += __shfl_xor_sync(0xffffffffu, s, o);
    if (lane == 0) out[w] = s + bfc[0];
}

// ---------------- launch -----------------------------------------------------
extern "C" void kernel_launch(void* const* d_in, const int* in_sizes, int n_in,
                              void* d_out, int out_size)
{
    const float* x   = (const float*)d_in[0];
    const int*   ei  = (const int*)d_in[1];
    const float* Wm  = (const float*)d_in[2];
    const float* bm  = (const float*)d_in[3];
    const float* Wc  = (const float*)d_in[4];
    const float* bc  = (const float*)d_in[5];
    const float* Wg1 = (const float*)d_in[6];
    const float* bg1 = (const float*)d_in[7];
    const float* Wg2 = (const float*)d_in[8];
    const float* bg2 = (const float*)d_in[9];
    const float* Wg3 = (const float*)d_in[10];
    const float* bg3 = (const float*)d_in[11];
    const float* e1g = (const float*)d_in[12];
    const float* e1b = (const float*)d_in[13];
    const float* e1m = (const float*)d_in[14];
    const float* e1v = (const float*)d_in[15];
    const float* e1W = (const float*)d_in[16];
    const float* e2g = (const float*)d_in[17];
    const float* e2b = (const float*)d_in[18];
    const float* e2m = (const float*)d_in[19];
    const float* e2v = (const float*)d_in[20];
    const float* e2W = (const float*)d_in[21];
    const float* e3g = (const float*)d_in[22];
    const float* e3b = (const float*)d_in[23];
    const float* e3m = (const float*)d_in[24];
    const float* e3v = (const float*)d_in[25];
    const float* e3W = (const float*)d_in[26];
    const float* Wfc = (const float*)d_in[27];
    const float* bfc = (const float*)d_in[28];
    float* out = (float*)d_out;

    const int n = in_sizes[0] / 512;
    const int E = in_sizes[1] / 2;
    const int* src = ei;
    const int* dst = ei + E;

    float *p_x0, *p_tmp, *p_bufA, *p_bufB, *p_nt, *p_scl, *p_shl;
    unsigned* p_mkey;
    int* p_deg;
    uint32_t *p0h, *p0l, *p1h, *p1l, *p2h, *p2l;
    cudaGetSymbolAddress((void**)&p_x0, g_x0);
    cudaGetSymbolAddress((void**)&p_tmp, g_tmp);
    cudaGetSymbolAddress((void**)&p_bufA, g_bufA);
    cudaGetSymbolAddress((void**)&p_bufB, g_bufB);
    cudaGetSymbolAddress((void**)&p_nt, g_nt);
    cudaGetSymbolAddress((void**)&p_mkey, g_mkey);
    cudaGetSymbolAddress((void**)&p_deg, g_deg);
    cudaGetSymbolAddress((void**)&p_scl, g_scl);
    cudaGetSymbolAddress((void**)&p_shl, g_shl);
    cudaGetSymbolAddress((void**)&p0h, g_wp0h);
    cudaGetSymbolAddress((void**)&p0l, g_wp0l);
    cudaGetSymbolAddress((void**)&p1h, g_wp1h);
    cudaGetSymbolAddress((void**)&p1l, g_wp1l);
    cudaGetSymbolAddress((void**)&p2h, g_wp2h);
    cudaGetSymbolAddress((void**)&p2l, g_wp2l);

    const int mb = (n + 63) / 64;
    const int THR = 256;
    auto blks = [&](int work) { return (work + THR - 1) / THR; };
    const int eb = (E + 127) / 128;

    // weight prep (deterministic every launch)
    k_prep_w<<<blks(128 * 128), THR>>>(e1W, e1g, e1b, e1m, e1v, 256, p0h, p0l, p_scl, p_shl);
    k_prep_w<<<blks(64 * 128), THR>>>(e2W, e2g, e2b, e2m, e2v, 128, p1h, p1l, p_scl + 256, p_shl + 256);
    k_prep_w<<<blks(64 * 128), THR>>>(e3W, e3g, e3b, e3m, e3v, 128, p2h, p2l, p_scl + 384, p_shl + 384);

    // degrees + normalization
    k_zero_i32<<<blks(n), THR>>>(p_deg, n);
    k_count_deg<<<blks(E), THR>>>(dst, E);
    k_dinv<<<blks(n), THR>>>(n);

    // input projection
    k_proj<<<mb, THR>>>(x, Wm, bm, Wc, bc, p_x0, n);

    // GCN (aggregate-first): agg = D^-1/2 (A+I) D^-1/2 X ; out = agg @ W + b
    k_gcn_init<<<blks(n * 64), THR>>>(p_x0, p_tmp, n, 64);
    k_gcn_edge<<<(E + 7) / 8, THR>>>(p_x0, src, dst, p_tmp, E, 16);
    k_gemm<128, false><<<dim3(mb, 1), THR>>>(p_tmp, Wg1, p_bufA, n, 64, 128,
                                             nullptr, nullptr, nullptr, nullptr, bg1);

    k_gcn_init<<<blks(n * 128), THR>>>(p_bufA, p_tmp, n, 128);
    k_gcn_edge<<<(E + 7) / 8, THR>>>(p_bufA, src, dst, p_tmp, E, 32);
    k_gemm<128, false><<<dim3(mb, 1), THR>>>(p_tmp, Wg2, p_bufB, n, 128, 128,
                                             nullptr, nullptr, nullptr, nullptr, bg2);

    k_gcn_init<<<blks(n * 128), THR>>>(p_bufB, p_tmp, n, 128);
    k_gcn_edge<<<(E + 7) / 8, THR>>>(p_bufB, src, dst, p_tmp, E, 32);
    k_gemm<128, false><<<dim3(mb, 2), THR>>>(p_tmp, Wg3, p_bufA, n, 128, 256,
                                             nullptr, nullptr, nullptr, nullptr, bg3);

    // EdgeConv 1: C=256 (in bufA -> out bufB)
    k_gemm<128, true><<<dim3(mb, 1), THR>>>(p_bufA, e1W, p_nt, n, 256, 128,
                                            e1g, e1b, e1m, e1v, nullptr);
    k_zero_u32<<<blks(n * 128), THR>>>(p_mkey, n * 128);
    k_ec_mma<256><<<eb, THR>>>(p_bufA, src, dst, p0h, p0l, p_scl, p_shl, p_mkey, E);
    k_ec_final<<<blks(n * 128), THR>>>(p_nt, p_mkey, p_bufB, n);

    // EdgeConv 2: C=128 (in bufB -> out tmp)
    k_gemm<128, true><<<dim3(mb, 1), THR>>>(p_bufB, e2W, p_nt, n, 128, 128,
                                            e2g, e2b, e2m, e2v, nullptr);
    k_zero_u32<<<blks(n * 128), THR>>>(p_mkey, n * 128);
    k_ec_mma<128><<<eb, THR>>>(p_bufB, src, dst, p1h, p1l, p_scl + 256, p_shl + 256, p_mkey, E);
    k_ec_final<<<blks(n * 128), THR>>>(p_nt, p_mkey, p_tmp, n);

    // EdgeConv 3: C=128 (in tmp -> out bufA)
    k_gemm<128, true><<<dim3(mb, 1), THR>>>(p_tmp, e3W, p_nt, n, 128, 128,
                                            e3g, e3b, e3m, e3v, nullptr);
    k_zero_u32<<<blks(n * 128), THR>>>(p_mkey, n * 128);
    k_ec_mma<128><<<eb, THR>>>(p_tmp, src, dst, p2h, p2l, p_scl + 384, p_shl + 384, p_mkey, E);
    k_ec_final<<<blks(n * 128), THR>>>(p_nt, p_mkey, p_bufA, n);

    // final FC
    k_final<<<blks(n * 32), THR>>>(p_bufA, Wfc, bfc, out, n);
}

// round 11
// speedup vs baseline: 2.1224x; 1.1032x over previous
#include <cuda_runtime.h>
#include <cuda_bf16.h>
#include <cstdint>

#define EPSF 1e-5f

// ---------------- scratch ----------------------------------------------------
__device__ float    g_x0[20000 * 64];
__device__ float    g_tmp[20000 * 256];
__device__ float    g_bufA[20000 * 256];
__device__ float    g_bufB[20000 * 256];
__device__ float    g_nt[20000 * 128];
__device__ unsigned g_mkey[20000 * 128];
__device__ int      g_deg[20000];
__device__ float    g_dinv[20000];
// pair-packed bf16 weights: [chunk k/32][n:Nout][kp:16] u32 = (bf16 k, bf16 k+1)
__device__ uint32_t g_we1h[16384], g_we1l[16384];   // e1 edge (bottom 256 rows)
__device__ uint32_t g_we2h[8192],  g_we2l[8192];    // e2 edge
__device__ uint32_t g_we3h[8192],  g_we3l[8192];    // e3 edge
__device__ uint32_t g_wn1h[16384], g_wn1l[16384];   // e1 node (top 256 rows)
__device__ uint32_t g_wn2h[8192],  g_wn2l[8192];    // e2 node
__device__ uint32_t g_wn3h[8192],  g_wn3l[8192];    // e3 node
__device__ uint32_t g_wmh[16384],  g_wml[16384];    // proj main (512x64)
__device__ uint32_t g_wch[16384],  g_wcl[16384];    // proj conv (512x64)
__device__ uint32_t g_wg1h[4096],  g_wg1l[4096];    // Wg1 (64x128)
__device__ uint32_t g_wg2h[8192],  g_wg2l[8192];    // Wg2 (128x128)
__device__ uint32_t g_wg3h[16384], g_wg3l[16384];   // Wg3 (128x256)
__device__ float g_scl[512], g_shl[512];            // BN bottom-half (edge path)
__device__ float g_sct[512], g_sht[512];            // BN top-half (node path)

// ---------------- helpers ----------------------------------------------------
__device__ __forceinline__ unsigned fenc(float f) {
    unsigned b = __float_as_uint(f);
    return (b & 0x80000000u) ? ~b : (b | 0x80000000u);
}
__device__ __forceinline__ float fdec(unsigned u) {
    return (u & 0x80000000u) ? __uint_as_float(u & 0x7fffffffu) : __uint_as_float(~u);
}
__device__ __forceinline__ unsigned packbf(__nv_bfloat16 a, __nv_bfloat16 b) {
    return ((unsigned)__bfloat16_as_ushort(b) << 16) | (unsigned)__bfloat16_as_ushort(a);
}
__device__ __forceinline__ void mma_bf16(float* c, const uint32_t* a, uint32_t b0, uint32_t b1) {
    asm volatile(
        "mma.sync.aligned.m16n8k16.row.col.f32.bf16.bf16.f32 "
        "{%0,%1,%2,%3}, {%4,%5,%6,%7}, {%8,%9}, {%0,%1,%2,%3};"
        : "+f"(c[0]), "+f"(c[1]), "+f"(c[2]), "+f"(c[3])
        : "r"(a[0]), "r"(a[1]), "r"(a[2]), "r"(a[3]), "r"(b0), "r"(b1));
}
// split f32 -> (hi, lo) packed pair builder
__device__ __forceinline__ void split2(float u0, float u1, uint32_t& hi, uint32_t& lo) {
    __nv_bfloat16 h0 = __float2bfloat16_rn(u0);
    __nv_bfloat16 h1 = __float2bfloat16_rn(u1);
    hi = packbf(h0, h1);
    lo = packbf(__float2bfloat16_rn(u0 - __bfloat162float(h0)),
                __float2bfloat16_rn(u1 - __bfloat162float(h1)));
}

// ---------------- tiny kernels -----------------------------------------------
__global__ void k_zero_i32(int* p, int n) {
    int i = blockIdx.x * blockDim.x + threadIdx.x;
    if (i < n) p[i] = 0;
}
__global__ void k_zero_u32(unsigned* p, int n) {
    int i = blockIdx.x * blockDim.x + threadIdx.x;
    if (i < n) p[i] = 0u;
}
__global__ void k_count_deg(const int* __restrict__ dst, int E) {
    int i = blockIdx.x * blockDim.x + threadIdx.x;
    if (i < E) atomicAdd(&g_deg[dst[i]], 1);
}
__global__ void k_dinv(int n) {
    int i = blockIdx.x * blockDim.x + threadIdx.x;
    if (i < n) g_dinv[i] = rsqrtf((float)(g_deg[i] + 1));
}

// ---------------- weight pack: W[K][Nout] -> pair-packed hi/lo ---------------
__global__ void k_pack(const float* __restrict__ W, int K, int Nout,
                       uint32_t* __restrict__ bh, uint32_t* __restrict__ bl)
{
    int idx = blockIdx.x * blockDim.x + threadIdx.x;
    if (idx >= (K / 2) * Nout) return;
    int n = idx % Nout, kp = idx / Nout;
    float w0 = W[(size_t)(kp * 2 + 0) * Nout + n];
    float w1 = W[(size_t)(kp * 2 + 1) * Nout + n];
    uint32_t hi, lo;
    split2(w0, w1, hi, lo);
    int o = ((kp >> 4) * Nout + n) * 16 + (kp & 15);
    bh[o] = hi;
    bl[o] = lo;
}
__global__ void k_bn(const float* __restrict__ gamma, const float* __restrict__ beta,
                     const float* __restrict__ mean, const float* __restrict__ var,
                     int C, float* __restrict__ sc, float* __restrict__ sh)
{
    int k = blockIdx.x * blockDim.x + threadIdx.x;
    if (k >= C) return;
    float s = gamma[k] * rsqrtf(var[k] + EPSF);
    sc[k] = s;
    sh[k] = beta[k] - mean[k] * s;
}

// ---------------- generic mma GEMM: C[M,Nout] = op(A)@W (+bias) --------------
// BN = block cols (64/128). BNR: A'=relu(A*sc+sh). SEL: 0 all rows,
// 1 write rows m%4==0 only, 2 write rows m%4!=0 only.
template <int BN, int BNR, int SEL>
__global__ __launch_bounds__(256, 2) void k_mm(
    const float* __restrict__ A, const uint32_t* __restrict__ wh,
    const uint32_t* __restrict__ wl, float* __restrict__ C_,
    int M, int K, int Nout,
    const float* __restrict__ scv, const float* __restrict__ shv,
    const float* __restrict__ bias)
{
    constexpr int NF = BN / 16;      // n-frags per warp
    constexpr int HALF = BN / 2;
    __shared__ uint32_t As_h[128 * 20], As_l[128 * 20];
    __shared__ uint32_t Bs_h[BN * 20], Bs_l[BN * 20];
    __shared__ float s_sc[BNR ? 512 : 1], s_sh[BNR ? 512 : 1];

    const int tid = threadIdx.x;
    const int w = tid >> 5, lane = tid & 31;
    const int wm = w & 3, wn = w >> 2;
    const int gr = lane >> 2, gc2 = lane & 3;
    const int m0 = blockIdx.x * 128;
    const int n0 = blockIdx.y * BN;

    if (BNR) {
        for (int k = tid; k < K; k += 256) { s_sc[k] = scv[k]; s_sh[k] = shv[k]; }
        __syncthreads();
    }

    const int r = tid >> 1, hh = tid & 1;
    int mrow = m0 + r;
    if (mrow >= M) mrow = M - 1;
    const float* Ar = A + (size_t)mrow * K + hh * 16;

    float acc[2][NF][4];
#pragma unroll
    for (int a = 0; a < 2; a++)
#pragma unroll
        for (int b = 0; b < NF; b++)
#pragma unroll
            for (int c = 0; c < 4; c++) acc[a][b][c] = 0.f;

#pragma unroll 1
    for (int kc = 0; kc < K / 32; kc++) {
        // stage B chunk
        const uint32_t* gh = wh + ((size_t)kc * Nout + n0) * 16;
        const uint32_t* gl = wl + ((size_t)kc * Nout + n0) * 16;
#pragma unroll
        for (int i = tid; i < 16 * BN; i += 256) {
            int nn = i >> 4, kp = i & 15;
            Bs_h[nn * 20 + kp] = gh[i];
            Bs_l[nn * 20 + kp] = gl[i];
        }
        // stage A (2 threads/row, 16 k each)
        {
            const float4* a4 = (const float4*)(Ar + kc * 32);
            uint32_t* ph = &As_h[r * 20 + hh * 8];
            uint32_t* pl = &As_l[r * 20 + hh * 8];
            if (BNR) {
                const float4* s4 = (const float4*)(s_sc + kc * 32 + hh * 16);
                const float4* t4 = (const float4*)(s_sh + kc * 32 + hh * 16);
#pragma unroll
                for (int j = 0; j < 4; j++) {
                    float4 a = a4[j], s = s4[j], t = t4[j];
                    float u0 = fmaxf(fmaf(a.x, s.x, t.x), 0.f);
                    float u1 = fmaxf(fmaf(a.y, s.y, t.y), 0.f);
                    float u2 = fmaxf(fmaf(a.z, s.z, t.z), 0.f);
                    float u3 = fmaxf(fmaf(a.w, s.w, t.w), 0.f);
                    split2(u0, u1, ph[2 * j + 0], pl[2 * j + 0]);
                    split2(u2, u3, ph[2 * j + 1], pl[2 * j + 1]);
                }
            } else {
#pragma unroll
                for (int j = 0; j < 4; j++) {
                    float4 a = a4[j];
                    split2(a.x, a.y, ph[2 * j + 0], pl[2 * j + 0]);
                    split2(a.z, a.w, ph[2 * j + 1], pl[2 * j + 1]);
                }
            }
        }
        __syncthreads();
#pragma unroll
        for (int kk = 0; kk < 2; kk++) {
            uint32_t ah[2][4], al[2][4];
#pragma unroll
            for (int mf = 0; mf < 2; mf++) {
                int r0 = (wm * 32 + mf * 16 + gr) * 20 + kk * 8 + gc2;
                ah[mf][0] = As_h[r0];
                ah[mf][1] = As_h[r0 + 160];
                ah[mf][2] = As_h[r0 + 4];
                ah[mf][3] = As_h[r0 + 164];
                al[mf][0] = As_l[r0];
                al[mf][1] = As_l[r0 + 160];
                al[mf][2] = As_l[r0 + 4];
                al[mf][3] = As_l[r0 + 164];
            }
#pragma unroll
            for (int nf = 0; nf < NF; nf++) {
                int nb = (wn * HALF + nf * 8 + gr) * 20 + kk * 8 + gc2;
                uint32_t b0h = Bs_h[nb], b1h = Bs_h[nb + 4];
                uint32_t b0l = Bs_l[nb], b1l = Bs_l[nb + 4];
#pragma unroll
                for (int mf = 0; mf < 2; mf++) {
                    mma_bf16(acc[mf][nf], ah[mf], b0h, b1h);
                    mma_bf16(acc[mf][nf], ah[mf], b0l, b1l);
                    mma_bf16(acc[mf][nf], al[mf], b0h, b1h);
                }
            }
        }
        __syncthreads();
    }

    // epilogue
#pragma unroll
    for (int mf = 0; mf < 2; mf++) {
        int m_a = m0 + wm * 32 + mf * 16 + gr;
        int m_b = m_a + 8;
        bool va = (m_a < M) && (SEL == 0 || (SEL == 1 ? ((m_a & 3) == 0) : ((m_a & 3) != 0)));
        bool vb = (m_b < M) && (SEL == 0 || (SEL == 1 ? ((m_b & 3) == 0) : ((m_b & 3) != 0)));
#pragma unroll
        for (int nf = 0; nf < NF; nf++) {
            int col = n0 + wn * HALF + nf * 8 + gc2 * 2;
            float bx = bias ? bias[col] : 0.f;
            float by = bias ? bias[col + 1] : 0.f;
            if (va) {
                float2 v = make_float2(acc[mf][nf][0] + bx, acc[mf][nf][1] + by);
                *(float2*)&C_[(size_t)m_a * Nout + col] = v;
            }
            if (vb) {
                float2 v = make_float2(acc[mf][nf][2] + bx, acc[mf][nf][3] + by);
                *(float2*)&C_[(size_t)m_b * Nout + col] = v;
            }
        }
    }
}

// ---------------- GCN aggregation (aggregate-first) --------------------------
__global__ void k_gcn_init(const float* __restrict__ in, float* __restrict__ out,
                           int n, int Wd)
{
    int idx = blockIdx.x * blockDim.x + threadIdx.x;
    if (idx < n * Wd) {
        int i = idx / Wd;
        float dv = g_dinv[i];
        out[idx] = in[idx] * dv * dv;
    }
}
__global__ void k_gcn_edge(const float* __restrict__ xin,
                           const int* __restrict__ src, const int* __restrict__ dst,
                           float* __restrict__ out, int E, int W4)
{
    int g = blockIdx.x * blockDim.x + threadIdx.x;
    int e = g >> 5, lane = g & 31;
    if (e >= E) return;
    int s = src[e], d = dst[e];
    float coef = g_dinv[s] * g_dinv[d];
    const float4* ts = (const float4*)(xin + (size_t)s * W4 * 4);
    float4* od = (float4*)(out + (size_t)d * W4 * 4);
    for (int j = lane; j < W4; j += 32) {
        float4 v = ts[j];
        v.x *= coef; v.y *= coef; v.z *= coef; v.w *= coef;
        asm volatile("red.global.add.v4.f32 [%0], {%1,%2,%3,%4};"
                     :: "l"(od + j), "f"(v.x), "f"(v.y), "f"(v.z), "f"(v.w) : "memory");
    }
}

// ---------------- EdgeConv edge term: warp mma.sync bf16 hi/lo x3 ------------
template <int C>
__global__ __launch_bounds__(256, 2) void k_ec_mma(
    const float* __restrict__ xf, const int* __restrict__ src, const int* __restrict__ dst,
    const uint32_t* __restrict__ wph, const uint32_t* __restrict__ wpl,
    const float* __restrict__ scv, const float* __restrict__ shv,
    unsigned* __restrict__ mkey, int E)
{
    __shared__ uint32_t As_h[128 * 20], As_l[128 * 20];
    __shared__ uint32_t Bs_h[128 * 20], Bs_l[128 * 20];
    __shared__ int s_srcsh[128], s_dst[128];

    const int tid = threadIdx.x;
    const int w = tid >> 5, lane = tid & 31;
    const int wm = w & 3, wn = w >> 2;
    const int gr = lane >> 2, gc2 = lane & 3;
    const int e0 = blockIdx.x * 128;

    if (tid < 128) {
        int e = e0 + tid;
        s_srcsh[tid] = (e < E) ? src[e] : 0;
        s_dst[tid]   = (e < E) ? dst[e] : 0;
    }
    __syncthreads();

    const int r = tid >> 1, hh = tid & 1;
    const float* xs0 = xf + (size_t)s_srcsh[r] * C + hh * 16;
    const float* xd0 = xf + (size_t)s_dst[r] * C + hh * 16;

    float acc[2][8][4];
#pragma unroll
    for (int a = 0; a < 2; a++)
#pragma unroll
        for (int b = 0; b < 8; b++)
#pragma unroll
            for (int c = 0; c < 4; c++) acc[a][b][c] = 0.f;

#pragma unroll 1
    for (int kc = 0; kc < C / 32; kc++) {
        const uint32_t* gh = wph + kc * 2048;
        const uint32_t* gl = wpl + kc * 2048;
#pragma unroll
        for (int i = tid; i < 2048; i += 256) {
            int nn = i >> 4, kp = i & 15;
            Bs_h[nn * 20 + kp] = gh[i];
            Bs_l[nn * 20 + kp] = gl[i];
        }
        {
            const float4* xs = (const float4*)(xs0 + kc * 32);
            const float4* xd = (const float4*)(xd0 + kc * 32);
            const float4* s4 = (const float4*)(scv + kc * 32 + hh * 16);
            const float4* t4 = (const float4*)(shv + kc * 32 + hh * 16);
            uint32_t* ph = &As_h[r * 20 + hh * 8];
            uint32_t* pl = &As_l[r * 20 + hh * 8];
#pragma unroll
            for (int j = 0; j < 4; j++) {
                float4 a = xs[j], d = xd[j], s = s4[j], t = t4[j];
                float u0 = fmaxf(fmaf(a.x - d.x, s.x, t.x), 0.f);
                float u1 = fmaxf(fmaf(a.y - d.y, s.y, t.y), 0.f);
                float u2 = fmaxf(fmaf(a.z - d.z, s.z, t.z), 0.f);
                float u3 = fmaxf(fmaf(a.w - d.w, s.w, t.w), 0.f);
                split2(u0, u1, ph[2 * j + 0], pl[2 * j + 0]);
                split2(u2, u3, ph[2 * j + 1], pl[2 * j + 1]);
            }
        }
        __syncthreads();
#pragma unroll
        for (int kk = 0; kk < 2; kk++) {
            uint32_t ah[2][4], al[2][4];
#pragma unroll
            for (int mf = 0; mf < 2; mf++) {
                int r0 = (wm * 32 + mf * 16 + gr) * 20 + kk * 8 + gc2;
                ah[mf][0] = As_h[r0];
                ah[mf][1] = As_h[r0 + 160];
                ah[mf][2] = As_h[r0 + 4];
                ah[mf][3] = As_h[r0 + 164];
                al[mf][0] = As_l[r0];
                al[mf][1] = As_l[r0 + 160];
                al[mf][2] = As_l[r0 + 4];
                al[mf][3] = As_l[r0 + 164];
            }
#pragma unroll
            for (int nf = 0; nf < 8; nf++) {
                int nb = (wn * 64 + nf * 8 + gr) * 20 + kk * 8 + gc2;
                uint32_t b0h = Bs_h[nb], b1h = Bs_h[nb + 4];
                uint32_t b0l = Bs_l[nb], b1l = Bs_l[nb + 4];
#pragma unroll
                for (int mf = 0; mf < 2; mf++) {
                    mma_bf16(acc[mf][nf], ah[mf], b0h, b1h);
                    mma_bf16(acc[mf][nf], ah[mf], b0l, b1l);
                    mma_bf16(acc[mf][nf], al[mf], b0h, b1h);
                }
            }
        }
        __syncthreads();
    }

#pragma unroll
    for (int mf = 0; mf < 2; mf++) {
        int er0 = wm * 32 + mf * 16 + gr;
        int er1 = er0 + 8;
        bool v0 = (e0 + er0 < E), v1 = (e0 + er1 < E);
        unsigned* base0 = mkey + (size_t)s_dst[er0] * 128;
        unsigned* base1 = mkey + (size_t)s_dst[er1] * 128;
#pragma unroll
        for (int nf = 0; nf < 8; nf++) {
            int col = wn * 64 + nf * 8 + gc2 * 2;
            if (v0) {
                atomicMax(base0 + col,     fenc(acc[mf][nf][0]));
                atomicMax(base0 + col + 1, fenc(acc[mf][nf][1]));
            }
            if (v1) {
                atomicMax(base1 + col,     fenc(acc[mf][nf][2]));
                atomicMax(base1 + col + 1, fenc(acc[mf][nf][3]));
            }
        }
    }
}

__global__ void k_ec_final(const float* __restrict__ a, const unsigned* __restrict__ mk,
                           float* __restrict__ h, int n)
{
    int idx = blockIdx.x * blockDim.x + threadIdx.x;
    if (idx < n * 128) {
        int i = idx >> 7;
        h[idx] = (g_deg[i] > 0) ? (a[idx] + fdec(mk[idx])) : 0.f;
    }
}

__global__ void k_final(const float* __restrict__ h, const float* __restrict__ Wfc,
                        const float* __restrict__ bfc, float* __restrict__ out, int n)
{
    int g = blockIdx.x * blockDim.x + threadIdx.x;
    int w = g >> 5, lane = g & 31;
    if (w >= n) return;
    float4 a = *(const float4*)&h[(size_t)w * 128 + lane * 4];
    float4 ww = *(const float4*)&Wfc[lane * 4];
    float s = a.x * ww.x + a.y * ww.y + a.z * ww.z + a.w * ww.w;
#pragma unroll
    for (int o = 16; o > 0; o >>= 1) s += __shfl_xor_sync(0xffffffffu, s, o);
    if (lane == 0) out[w] = s + bfc[0];
}

// ---------------- launch -----------------------------------------------------
extern "C" void kernel_launch(void* const* d_in, const int* in_sizes, int n_in,
                              void* d_out, int out_size)
{
    const float* x   = (const float*)d_in[0];
    const int*   ei  = (const int*)d_in[1];
    const float* Wm  = (const float*)d_in[2];
    const float* bm  = (const float*)d_in[3];
    const float* Wc  = (const float*)d_in[4];
    const float* bc  = (const float*)d_in[5];
    const float* Wg1 = (const float*)d_in[6];
    const float* bg1 = (const float*)d_in[7];
    const float* Wg2 = (const float*)d_in[8];
    const float* bg2 = (const float*)d_in[9];
    const float* Wg3 = (const float*)d_in[10];
    const float* bg3 = (const float*)d_in[11];
    const float* e1g = (const float*)d_in[12];
    const float* e1b = (const float*)d_in[13];
    const float* e1m = (const float*)d_in[14];
    const float* e1v = (const float*)d_in[15];
    const float* e1W = (const float*)d_in[16];
    const float* e2g = (const float*)d_in[17];
    const float* e2b = (const float*)d_in[18];
    const float* e2m = (const float*)d_in[19];
    const float* e2v = (const float*)d_in[20];
    const float* e2W = (const float*)d_in[21];
    const float* e3g = (const float*)d_in[22];
    const float* e3b = (const float*)d_in[23];
    const float* e3m = (const float*)d_in[24];
    const float* e3v = (const float*)d_in[25];
    const float* e3W = (const float*)d_in[26];
    const float* Wfc = (const float*)d_in[27];
    const float* bfc = (const float*)d_in[28];
    float* out = (float*)d_out;

    const int n = in_sizes[0] / 512;
    const int E = in_sizes[1] / 2;
    const int* src = ei;
    const int* dst = ei + E;

    float *p_x0, *p_tmp, *p_bufA, *p_bufB, *p_nt;
    float *p_scl, *p_shl, *p_sct, *p_sht;
    unsigned* p_mkey;
    int* p_deg;
    uint32_t *we1h, *we1l, *we2h, *we2l, *we3h, *we3l;
    uint32_t *wn1h, *wn1l, *wn2h, *wn2l, *wn3h, *wn3l;
    uint32_t *wmh, *wml, *wch, *wcl;
    uint32_t *wg1h, *wg1l, *wg2h, *wg2l, *wg3h, *wg3l;
    cudaGetSymbolAddress((void**)&p_x0, g_x0);
    cudaGetSymbolAddress((void**)&p_tmp, g_tmp);
    cudaGetSymbolAddress((void**)&p_bufA, g_bufA);
    cudaGetSymbolAddress((void**)&p_bufB, g_bufB);
    cudaGetSymbolAddress((void**)&p_nt, g_nt);
    cudaGetSymbolAddress((void**)&p_mkey, g_mkey);
    cudaGetSymbolAddress((void**)&p_deg, g_deg);
    cudaGetSymbolAddress((void**)&p_scl, g_scl);
    cudaGetSymbolAddress((void**)&p_shl, g_shl);
    cudaGetSymbolAddress((void**)&p_sct, g_sct);
    cudaGetSymbolAddress((void**)&p_sht, g_sht);
    cudaGetSymbolAddress((void**)&we1h, g_we1h); cudaGetSymbolAddress((void**)&we1l, g_we1l);
    cudaGetSymbolAddress((void**)&we2h, g_we2h); cudaGetSymbolAddress((void**)&we2l, g_we2l);
    cudaGetSymbolAddress((void**)&we3h, g_we3h); cudaGetSymbolAddress((void**)&we3l, g_we3l);
    cudaGetSymbolAddress((void**)&wn1h, g_wn1h); cudaGetSymbolAddress((void**)&wn1l, g_wn1l);
    cudaGetSymbolAddress((void**)&wn2h, g_wn2h); cudaGetSymbolAddress((void**)&wn2l, g_wn2l);
    cudaGetSymbolAddress((void**)&wn3h, g_wn3h); cudaGetSymbolAddress((void**)&wn3l, g_wn3l);
    cudaGetSymbolAddress((void**)&wmh, g_wmh);   cudaGetSymbolAddress((void**)&wml, g_wml);
    cudaGetSymbolAddress((void**)&wch, g_wch);   cudaGetSymbolAddress((void**)&wcl, g_wcl);
    cudaGetSymbolAddress((void**)&wg1h, g_wg1h); cudaGetSymbolAddress((void**)&wg1l, g_wg1l);
    cudaGetSymbolAddress((void**)&wg2h, g_wg2h); cudaGetSymbolAddress((void**)&wg2l, g_wg2l);
    cudaGetSymbolAddress((void**)&wg3h, g_wg3h); cudaGetSymbolAddress((void**)&wg3l, g_wg3l);

    const int THR = 256;
    auto blks = [&](int work) { return (work + THR - 1) / THR; };
    const int mb = (n + 127) / 128;
    const int eb = (E + 127) / 128;

    // ---- weight prep ----
    k_pack<<<blks(128 * 128), THR>>>(e1W + 256 * 128, 256, 128, we1h, we1l);
    k_pack<<<blks(64 * 128), THR>>>(e2W + 128 * 128, 128, 128, we2h, we2l);
    k_pack<<<blks(64 * 128), THR>>>(e3W + 128 * 128, 128, 128, we3h, we3l);
    k_pack<<<blks(128 * 128), THR>>>(e1W, 256, 128, wn1h, wn1l);
    k_pack<<<blks(64 * 128), THR>>>(e2W, 128, 128, wn2h, wn2l);
    k_pack<<<blks(64 * 128), THR>>>(e3W, 128, 128, wn3h, wn3l);
    k_pack<<<blks(256 * 64), THR>>>(Wm, 512, 64, wmh, wml);
    k_pack<<<blks(256 * 64), THR>>>(Wc, 512, 64, wch, wcl);
    k_pack<<<blks(32 * 128), THR>>>(Wg1, 64, 128, wg1h, wg1l);
    k_pack<<<blks(64 * 128), THR>>>(Wg2, 128, 128, wg2h, wg2l);
    k_pack<<<blks(64 * 256), THR>>>(Wg3, 128, 256, wg3h, wg3l);
    k_bn<<<1, 256>>>(e1g + 256, e1b + 256, e1m + 256, e1v + 256, 256, p_scl, p_shl);
    k_bn<<<1, 128>>>(e2g + 128, e2b + 128, e2m + 128, e2v + 128, 128, p_scl + 256, p_shl + 256);
    k_bn<<<1, 128>>>(e3g + 128, e3b + 128, e3m + 128, e3v + 128, 128, p_scl + 384, p_shl + 384);
    k_bn<<<1, 256>>>(e1g, e1b, e1m, e1v, 256, p_sct, p_sht);
    k_bn<<<1, 128>>>(e2g, e2b, e2m, e2v, 128, p_sct + 256, p_sht + 256);
    k_bn<<<1, 128>>>(e3g, e3b, e3m, e3v, 128, p_sct + 384, p_sht + 384);

    // ---- degrees + normalization ----
    k_zero_i32<<<blks(n), THR>>>(p_deg, n);
    k_count_deg<<<blks(E), THR>>>(dst, E);
    k_dinv<<<blks(n), THR>>>(n);

    // ---- input projection (two row-predicated GEMMs into same buffer) ----
    k_mm<64, 0, 1><<<dim3(mb, 1), THR>>>(x, wmh, wml, p_x0, n, 512, 64, nullptr, nullptr, bm);
    k_mm<64, 0, 2><<<dim3(mb, 1), THR>>>(x, wch, wcl, p_x0, n, 512, 64, nullptr, nullptr, bc);

    // ---- GCN (aggregate-first): agg = D^-1/2 (A+I) D^-1/2 X; out = agg@W + b
    k_gcn_init<<<blks(n * 64), THR>>>(p_x0, p_tmp, n, 64);
    k_gcn_edge<<<(E + 7) / 8, THR>>>(p_x0, src, dst, p_tmp, E, 16);
    k_mm<128, 0, 0><<<dim3(mb, 1), THR>>>(p_tmp, wg1h, wg1l, p_bufA, n, 64, 128,
                                          nullptr, nullptr, bg1);

    k_gcn_init<<<blks(n * 128), THR>>>(p_bufA, p_tmp, n, 128);
    k_gcn_edge<<<(E + 7) / 8, THR>>>(p_bufA, src, dst, p_tmp, E, 32);
    k_mm<128, 0, 0><<<dim3(mb, 1), THR>>>(p_tmp, wg2h, wg2l, p_bufB, n, 128, 128,
                                          nullptr, nullptr, bg2);

    k_gcn_init<<<blks(n * 128), THR>>>(p_bufB, p_tmp, n, 128);
    k_gcn_edge<<<(E + 7) / 8, THR>>>(p_bufB, src, dst, p_tmp, E, 32);
    k_mm<128, 0, 0><<<dim3(mb, 2), THR>>>(p_tmp, wg3h, wg3l, p_bufA, n, 128, 256,
                                          nullptr, nullptr, bg3);

    // ---- EdgeConv 1: C=256 (in bufA -> out bufB) ----
    k_mm<128, 1, 0><<<dim3(mb, 1), THR>>>(p_bufA, wn1h, wn1l, p_nt, n, 256, 128,
                                          p_sct, p_sht, nullptr);
    k_zero_u32<<<blks(n * 128), THR>>>(p_mkey, n * 128);
    k_ec_mma<256><<<eb, THR>>>(p_bufA, src, dst, we1h, we1l, p_scl, p_shl, p_mkey, E);
    k_ec_final<<<blks(n * 128), THR>>>(p_nt, p_mkey, p_bufB, n);

    // ---- EdgeConv 2: C=128 (in bufB -> out tmp) ----
    k_mm<128, 1, 0><<<dim3(mb, 1), THR>>>(p_bufB, wn2h, wn2l, p_nt, n, 128, 128,
                                          p_sct + 256, p_sht + 256, nullptr);
    k_zero_u32<<<blks(n * 128), THR>>>(p_mkey, n * 128);
    k_ec_mma<128><<<eb, THR>>>(p_bufB, src, dst, we2h, we2l, p_scl + 256, p_shl + 256, p_mkey, E);
    k_ec_final<<<blks(n * 128), THR>>>(p_nt, p_mkey, p_tmp, n);

    // ---- EdgeConv 3: C=128 (in tmp -> out bufA) ----
    k_mm<128, 1, 0><<<dim3(mb, 1), THR>>>(p_tmp, wn3h, wn3l, p_nt, n, 128, 128,
                                          p_sct + 384, p_sht + 384, nullptr);
    k_zero_u32<<<blks(n * 128), THR>>>(p_mkey, n * 128);
    k_ec_mma<128><<<eb, THR>>>(p_tmp, src, dst, we3h, we3l, p_scl + 384, p_shl + 384, p_mkey, E);
    k_ec_final<<<blks(n * 128), THR>>>(p_nt, p_mkey, p_bufA, n);

    // ---- final FC ----
    k_final<<<blks(n * 32), THR>>>(p_bufA, Wfc, bfc, out, n);
}

// round 13
// speedup vs baseline: 2.2835x; 1.0759x over previous
#include <cuda_runtime.h>
#include <cuda_bf16.h>
#include <cstdint>
#include <math_constants.h>

#define EPSF 1e-5f

// ---------------- scratch ----------------------------------------------------
__device__ float    g_x0[20000 * 64];
__device__ float    g_tmp[20000 * 256];
__device__ float    g_bufA[20000 * 256];
__device__ float    g_bufB[20000 * 256];
__device__ float    g_nt[20000 * 128];
__device__ unsigned g_mkey[20000 * 128];
__device__ int      g_deg[20000];
__device__ float    g_dinv[20000];
__device__ int      g_off[20000];
__device__ int      g_cur[20000];
__device__ int      g_psrc[320000];
__device__ int      g_pdst[320000];
// pair-packed bf16 weights: [chunk k/32][n:Nout][kp:16] u32 = (bf16 k, bf16 k+1)
__device__ uint32_t g_we1h[16384], g_we1l[16384];
__device__ uint32_t g_we2h[8192],  g_we2l[8192];
__device__ uint32_t g_we3h[8192],  g_we3l[8192];
__device__ uint32_t g_wn1h[16384], g_wn1l[16384];
__device__ uint32_t g_wn2h[8192],  g_wn2l[8192];
__device__ uint32_t g_wn3h[8192],  g_wn3l[8192];
__device__ uint32_t g_wmh[16384],  g_wml[16384];
__device__ uint32_t g_wch[16384],  g_wcl[16384];
__device__ uint32_t g_wg1h[4096],  g_wg1l[4096];
__device__ uint32_t g_wg2h[8192],  g_wg2l[8192];
__device__ uint32_t g_wg3h[16384], g_wg3l[16384];
__device__ float g_scl[512], g_shl[512];
__device__ float g_sct[512], g_sht[512];

// ---------------- helpers ----------------------------------------------------
__device__ __forceinline__ unsigned fenc(float f) {
    unsigned b = __float_as_uint(f);
    return (b & 0x80000000u) ? ~b : (b | 0x80000000u);
}
__device__ __forceinline__ float fdec(unsigned u) {
    return (u & 0x80000000u) ? __uint_as_float(u & 0x7fffffffu) : __uint_as_float(~u);
}
__device__ __forceinline__ unsigned packbf(__nv_bfloat16 a, __nv_bfloat16 b) {
    return ((unsigned)__bfloat16_as_ushort(b) << 16) | (unsigned)__bfloat16_as_ushort(a);
}
__device__ __forceinline__ void mma_bf16(float* c, const uint32_t* a, uint32_t b0, uint32_t b1) {
    asm volatile(
        "mma.sync.aligned.m16n8k16.row.col.f32.bf16.bf16.f32 "
        "{%0,%1,%2,%3}, {%4,%5,%6,%7}, {%8,%9}, {%0,%1,%2,%3};"
        : "+f"(c[0]), "+f"(c[1]), "+f"(c[2]), "+f"(c[3])
        : "r"(a[0]), "r"(a[1]), "r"(a[2]), "r"(a[3]), "r"(b0), "r"(b1));
}
__device__ __forceinline__ void split2(float u0, float u1, uint32_t& hi, uint32_t& lo) {
    __nv_bfloat16 h0 = __float2bfloat16_rn(u0);
    __nv_bfloat16 h1 = __float2bfloat16_rn(u1);
    hi = packbf(h0, h1);
    lo = packbf(__float2bfloat16_rn(u0 - __bfloat162float(h0)),
                __float2bfloat16_rn(u1 - __bfloat162float(h1)));
}
__device__ __forceinline__ void red4(float* p, float4 v) {
    asm volatile("red.global.add.v4.f32 [%0], {%1,%2,%3,%4};"
                 :: "l"(p), "f"(v.x), "f"(v.y), "f"(v.z), "f"(v.w) : "memory");
}

// ---------------- tiny kernels -----------------------------------------------
__global__ void k_zero_i32(int* p, int n) {
    int i = blockIdx.x * blockDim.x + threadIdx.x;
    if (i < n) p[i] = 0;
}
__global__ void k_zero_u32(unsigned* p, int n) {
    int i = blockIdx.x * blockDim.x + threadIdx.x;
    if (i < n) p[i] = 0u;
}
__global__ void k_count_deg(const int* __restrict__ dst, int E) {
    int i = blockIdx.x * blockDim.x + threadIdx.x;
    if (i < E) atomicAdd(&g_deg[dst[i]], 1);
}
__global__ void k_dinv(int n) {
    int i = blockIdx.x * blockDim.x + threadIdx.x;
    if (i < n) g_dinv[i] = rsqrtf((float)(g_deg[i] + 1));
}
// single-block exclusive scan of g_deg -> g_off, also copy to g_cur
__global__ void k_scan(int n) {
    __shared__ int s[256];
    __shared__ int base_s;
    int tid = threadIdx.x;
    if (tid == 0) base_s = 0;
    __syncthreads();
    for (int c0 = 0; c0 < n; c0 += 256) {
        int i = c0 + tid;
        int v = (i < n) ? g_deg[i] : 0;
        s[tid] = v;
        __syncthreads();
#pragma unroll
        for (int o = 1; o < 256; o <<= 1) {
            int t = (tid >= o) ? s[tid - o] : 0;
            __syncthreads();
            s[tid] += t;
            __syncthreads();
        }
        if (i < n) {
            int ex = base_s + s[tid] - v;
            g_off[i] = ex;
            g_cur[i] = ex;
        }
        int tot = s[255];
        __syncthreads();
        if (tid == 0) base_s += tot;
        __syncthreads();
    }
}
__global__ void k_scatter(const int* __restrict__ src, const int* __restrict__ dst, int E) {
    int e = blockIdx.x * blockDim.x + threadIdx.x;
    if (e >= E) return;
    int d = dst[e];
    int p = atomicAdd(&g_cur[d], 1);
    g_psrc[p] = src[e];
    g_pdst[p] = d;
}

// ---------------- weight pack ------------------------------------------------
__global__ void k_pack(const float* __restrict__ W, int K, int Nout,
                       uint32_t* __restrict__ bh, uint32_t* __restrict__ bl)
{
    int idx = blockIdx.x * blockDim.x + threadIdx.x;
    if (idx >= (K / 2) * Nout) return;
    int n = idx % Nout, kp = idx / Nout;
    float w0 = W[(size_t)(kp * 2 + 0) * Nout + n];
    float w1 = W[(size_t)(kp * 2 + 1) * Nout + n];
    uint32_t hi, lo;
    split2(w0, w1, hi, lo);
    int o = ((kp >> 4) * Nout + n) * 16 + (kp & 15);
    bh[o] = hi;
    bl[o] = lo;
}
__global__ void k_bn(const float* __restrict__ gamma, const float* __restrict__ beta,
                     const float* __restrict__ mean, const float* __restrict__ var,
                     int C, float* __restrict__ sc, float* __restrict__ sh)
{
    int k = blockIdx.x * blockDim.x + threadIdx.x;
    if (k >= C) return;
    float s = gamma[k] * rsqrtf(var[k] + EPSF);
    sc[k] = s;
    sh[k] = beta[k] - mean[k] * s;
}

// ---------------- generic mma GEMM ------------------------------------------
template <int BN, int BNR, int SEL>
__global__ __launch_bounds__(256, 2) void k_mm(
    const float* __restrict__ A, const uint32_t* __restrict__ wh,
    const uint32_t* __restrict__ wl, float* __restrict__ C_,
    int M, int K, int Nout,
    const float* __restrict__ scv, const float* __restrict__ shv,
    const float* __restrict__ bias)
{
    constexpr int NF = BN / 16;
    constexpr int HALF = BN / 2;
    __shared__ uint32_t As_h[128 * 20], As_l[128 * 20];
    __shared__ uint32_t Bs_h[BN * 20], Bs_l[BN * 20];
    __shared__ float s_sc[BNR ? 512 : 1], s_sh[BNR ? 512 : 1];

    const int tid = threadIdx.x;
    const int w = tid >> 5, lane = tid & 31;
    const int wm = w & 3, wn = w >> 2;
    const int gr = lane >> 2, gc2 = lane & 3;
    const int m0 = blockIdx.x * 128;
    const int n0 = blockIdx.y * BN;

    if (BNR) {
        for (int k = tid; k < K; k += 256) { s_sc[k] = scv[k]; s_sh[k] = shv[k]; }
        __syncthreads();
    }

    const int r = tid >> 1, hh = tid & 1;
    int mrow = m0 + r;
    if (mrow >= M) mrow = M - 1;
    const float* Ar = A + (size_t)mrow * K + hh * 16;

    float acc[2][NF][4];
#pragma unroll
    for (int a = 0; a < 2; a++)
#pragma unroll
        for (int b = 0; b < NF; b++)
#pragma unroll
            for (int c = 0; c < 4; c++) acc[a][b][c] = 0.f;

#pragma unroll 1
    for (int kc = 0; kc < K / 32; kc++) {
        const uint32_t* gh = wh + ((size_t)kc * Nout + n0) * 16;
        const uint32_t* gl = wl + ((size_t)kc * Nout + n0) * 16;
#pragma unroll
        for (int i = tid; i < 16 * BN; i += 256) {
            int nn = i >> 4, kp = i & 15;
            Bs_h[nn * 20 + kp] = gh[i];
            Bs_l[nn * 20 + kp] = gl[i];
        }
        {
            const float4* a4 = (const float4*)(Ar + kc * 32);
            uint32_t* ph = &As_h[r * 20 + hh * 8];
            uint32_t* pl = &As_l[r * 20 + hh * 8];
            if (BNR) {
                const float4* s4 = (const float4*)(s_sc + kc * 32 + hh * 16);
                const float4* t4 = (const float4*)(s_sh + kc * 32 + hh * 16);
#pragma unroll
                for (int j = 0; j < 4; j++) {
                    float4 a = a4[j], s = s4[j], t = t4[j];
                    float u0 = fmaxf(fmaf(a.x, s.x, t.x), 0.f);
                    float u1 = fmaxf(fmaf(a.y, s.y, t.y), 0.f);
                    float u2 = fmaxf(fmaf(a.z, s.z, t.z), 0.f);
                    float u3 = fmaxf(fmaf(a.w, s.w, t.w), 0.f);
                    split2(u0, u1, ph[2 * j + 0], pl[2 * j + 0]);
                    split2(u2, u3, ph[2 * j + 1], pl[2 * j + 1]);
                }
            } else {
#pragma unroll
                for (int j = 0; j < 4; j++) {
                    float4 a = a4[j];
                    split2(a.x, a.y, ph[2 * j + 0], pl[2 * j + 0]);
                    split2(a.z, a.w, ph[2 * j + 1], pl[2 * j + 1]);
                }
            }
        }
        __syncthreads();
#pragma unroll
        for (int kk = 0; kk < 2; kk++) {
            uint32_t ah[2][4], al[2][4];
#pragma unroll
            for (int mf = 0; mf < 2; mf++) {
                int r0 = (wm * 32 + mf * 16 + gr) * 20 + kk * 8 + gc2;
                ah[mf][0] = As_h[r0];
                ah[mf][1] = As_h[r0 + 160];
                ah[mf][2] = As_h[r0 + 4];
                ah[mf][3] = As_h[r0 + 164];
                al[mf][0] = As_l[r0];
                al[mf][1] = As_l[r0 + 160];
                al[mf][2] = As_l[r0 + 4];
                al[mf][3] = As_l[r0 + 164];
            }
#pragma unroll
            for (int nf = 0; nf < NF; nf++) {
                int nb = (wn * HALF + nf * 8 + gr) * 20 + kk * 8 + gc2;
                uint32_t b0h = Bs_h[nb], b1h = Bs_h[nb + 4];
                uint32_t b0l = Bs_l[nb], b1l = Bs_l[nb + 4];
#pragma unroll
                for (int mf = 0; mf < 2; mf++) {
                    mma_bf16(acc[mf][nf], ah[mf], b0h, b1h);
                    mma_bf16(acc[mf][nf], ah[mf], b0l, b1l);
                    mma_bf16(acc[mf][nf], al[mf], b0h, b1h);
                }
            }
        }
        __syncthreads();
    }

#pragma unroll
    for (int mf = 0; mf < 2; mf++) {
        int m_a = m0 + wm * 32 + mf * 16 + gr;
        int m_b = m_a + 8;
        bool va = (m_a < M) && (SEL == 0 || (SEL == 1 ? ((m_a & 3) == 0) : ((m_a & 3) != 0)));
        bool vb = (m_b < M) && (SEL == 0 || (SEL == 1 ? ((m_b & 3) == 0) : ((m_b & 3) != 0)));
#pragma unroll
        for (int nf = 0; nf < NF; nf++) {
            int col = n0 + wn * HALF + nf * 8 + gc2 * 2;
            float bx = bias ? bias[col] : 0.f;
            float by = bias ? bias[col + 1] : 0.f;
            if (va) {
                float2 v = make_float2(acc[mf][nf][0] + bx, acc[mf][nf][1] + by);
                *(float2*)&C_[(size_t)m_a * Nout + col] = v;
            }
            if (vb) {
                float2 v = make_float2(acc[mf][nf][2] + bx, acc[mf][nf][3] + by);
                *(float2*)&C_[(size_t)m_b * Nout + col] = v;
            }
        }
    }
}

// ---------------- GCN aggregation --------------------------------------------
__global__ void k_gcn_init(const float* __restrict__ in, float* __restrict__ out,
                           int n, int Wd)
{
    int idx = blockIdx.x * blockDim.x + threadIdx.x;
    if (idx < n * Wd) {
        int i = idx / Wd;
        float dv = g_dinv[i];
        out[idx] = in[idx] * dv * dv;
    }
}
// warp handles 8 consecutive dst-sorted edges with run-length accumulation
__global__ void k_gcn_edge2(const float* __restrict__ xin, float* __restrict__ out,
                            int E, int W4)
{
    int gw = (blockIdx.x * blockDim.x + threadIdx.x) >> 5;
    int lane = threadIdx.x & 31;
    int e0 = gw * 8;
    if (e0 >= E) return;
    int e1 = min(e0 + 8, E);
    float4 a0 = make_float4(0.f, 0.f, 0.f, 0.f);
    float4 a1 = make_float4(0.f, 0.f, 0.f, 0.f);
    int dprev = -1;
    const bool l0 = lane < W4;
    const bool l1 = (W4 > 32) && (lane + 32 < W4);
    for (int e = e0; e < e1; e++) {
        int s = g_psrc[e], d = g_pdst[e];
        if (d != dprev && dprev >= 0) {
            float* od = out + (size_t)dprev * W4 * 4;
            if (l0) red4(od + lane * 4, a0);
            if (l1) red4(od + (lane + 32) * 4, a1);
            a0 = make_float4(0.f, 0.f, 0.f, 0.f);
            a1 = make_float4(0.f, 0.f, 0.f, 0.f);
        }
        dprev = d;
        float c = g_dinv[s] * g_dinv[d];
        const float4* ts = (const float4*)(xin + (size_t)s * W4 * 4);
        if (l0) {
            float4 v = ts[lane];
            a0.x = fmaf(v.x, c, a0.x); a0.y = fmaf(v.y, c, a0.y);
            a0.z = fmaf(v.z, c, a0.z); a0.w = fmaf(v.w, c, a0.w);
        }
        if (l1) {
            float4 v = ts[lane + 32];
            a1.x = fmaf(v.x, c, a1.x); a1.y = fmaf(v.y, c, a1.y);
            a1.z = fmaf(v.z, c, a1.z); a1.w = fmaf(v.w, c, a1.w);
        }
    }
    if (dprev >= 0) {
        float* od = out + (size_t)dprev * W4 * 4;
        if (l0) red4(od + lane * 4, a0);
        if (l1) red4(od + (lane + 32) * 4, a1);
    }
}

// ---------------- EdgeConv edge term: mma + segmented-max epilogue -----------
template <int C>
__global__ __launch_bounds__(256, 2) void k_ec_mma(
    const float* __restrict__ xf,
    const uint32_t* __restrict__ wph, const uint32_t* __restrict__ wpl,
    const float* __restrict__ scv, const float* __restrict__ shv,
    unsigned* __restrict__ mkey, int E)
{
    __shared__ uint32_t SM[10240];          // 40KB: staging, reused as D halves
    __shared__ int s_srcsh[128], s_dst[128];
    uint32_t* As_h = SM;
    uint32_t* As_l = SM + 2560;
    uint32_t* Bs_h = SM + 5120;
    uint32_t* Bs_l = SM + 7680;
    float* Ds = (float*)SM;                 // 128 x 68 floats = 34816 B

    const int tid = threadIdx.x;
    const int w = tid >> 5, lane = tid & 31;
    const int wm = w & 3, wn = w >> 2;
    const int gr = lane >> 2, gc2 = lane & 3;
    const int e0 = blockIdx.x * 128;

    if (tid < 128) {
        int e = e0 + tid;
        s_srcsh[tid] = (e < E) ? g_psrc[e] : 0;
        s_dst[tid]   = (e < E) ? g_pdst[e] : -1;
    }
    __syncthreads();

    const int r = tid >> 1, hh = tid & 1;
    const float* xs0 = xf + (size_t)s_srcsh[r] * C + hh * 16;
    const float* xd0 = xf + (size_t)max(s_dst[r], 0) * C + hh * 16;

    float acc[2][8][4];
#pragma unroll
    for (int a = 0; a < 2; a++)
#pragma unroll
        for (int b = 0; b < 8; b++)
#pragma unroll
            for (int c = 0; c < 4; c++) acc[a][b][c] = 0.f;

#pragma unroll 1
    for (int kc = 0; kc < C / 32; kc++) {
        const uint32_t* gh = wph + kc * 2048;
        const uint32_t* gl = wpl + kc * 2048;
#pragma unroll
        for (int i = tid; i < 2048; i += 256) {
            int nn = i >> 4, kp = i & 15;
            Bs_h[nn * 20 + kp] = gh[i];
            Bs_l[nn * 20 + kp] = gl[i];
        }
        {
            const float4* xs = (const float4*)(xs0 + kc * 32);
            const float4* xd = (const float4*)(xd0 + kc * 32);
            const float4* s4 = (const float4*)(scv + kc * 32 + hh * 16);
            const float4* t4 = (const float4*)(shv + kc * 32 + hh * 16);
            uint32_t* ph = &As_h[r * 20 + hh * 8];
            uint32_t* pl = &As_l[r * 20 + hh * 8];
#pragma unroll
            for (int j = 0; j < 4; j++) {
                float4 a = xs[j], d = xd[j], s = s4[j], t = t4[j];
                float u0 = fmaxf(fmaf(a.x - d.x, s.x, t.x), 0.f);
                float u1 = fmaxf(fmaf(a.y - d.y, s.y, t.y), 0.f);
                float u2 = fmaxf(fmaf(a.z - d.z, s.z, t.z), 0.f);
                float u3 = fmaxf(fmaf(a.w - d.w, s.w, t.w), 0.f);
                split2(u0, u1, ph[2 * j + 0], pl[2 * j + 0]);
                split2(u2, u3, ph[2 * j + 1], pl[2 * j + 1]);
            }
        }
        __syncthreads();
#pragma unroll
        for (int kk = 0; kk < 2; kk++) {
            uint32_t ah[2][4], al[2][4];
#pragma unroll
            for (int mf = 0; mf < 2; mf++) {
                int r0 = (wm * 32 + mf * 16 + gr) * 20 + kk * 8 + gc2;
                ah[mf][0] = As_h[r0];
                ah[mf][1] = As_h[r0 + 160];
                ah[mf][2] = As_h[r0 + 4];
                ah[mf][3] = As_h[r0 + 164];
                al[mf][0] = As_l[r0];
                al[mf][1] = As_l[r0 + 160];
                al[mf][2] = As_l[r0 + 4];
                al[mf][3] = As_l[r0 + 164];
            }
#pragma unroll
            for (int nf = 0; nf < 8; nf++) {
                int nb = (wn * 64 + nf * 8 + gr) * 20 + kk * 8 + gc2;
                uint32_t b0h = Bs_h[nb], b1h = Bs_h[nb + 4];
                uint32_t b0l = Bs_l[nb], b1l = Bs_l[nb + 4];
#pragma unroll
                for (int mf = 0; mf < 2; mf++) {
                    mma_bf16(acc[mf][nf], ah[mf], b0h, b1h);
                    mma_bf16(acc[mf][nf], ah[mf], b0l, b1l);
                    mma_bf16(acc[mf][nf], al[mf], b0h, b1h);
                }
            }
        }
        __syncthreads();
    }

    // segmented-max epilogue: two 64-col halves through smem
#pragma unroll 1
    for (int ch = 0; ch < 2; ch++) {
        __syncthreads();
        if (wn == ch) {
#pragma unroll
            for (int mf = 0; mf < 2; mf++) {
                int er0 = wm * 32 + mf * 16 + gr;
                int er1 = er0 + 8;
#pragma unroll
                for (int nf = 0; nf < 8; nf++) {
                    int col = nf * 8 + gc2 * 2;
                    Ds[er0 * 68 + col]     = acc[mf][nf][0];
                    Ds[er0 * 68 + col + 1] = acc[mf][nf][1];
                    Ds[er1 * 68 + col]     = acc[mf][nf][2];
                    Ds[er1 * 68 + col + 1] = acc[mf][nf][3];
                }
            }
        }
        __syncthreads();
        // 256 threads: 64 cols x 4 row-segments of 32
        {
            int col = tid & 63, seg = tid >> 6;
            int r0 = seg * 32, r1 = r0 + 32;
            float m = -CUDART_INF_F;
            int dprev = -1;
            for (int rr = r0; rr < r1; rr++) {
                int d = s_dst[rr];
                float v = (d >= 0) ? Ds[rr * 68 + col] : -CUDART_INF_F;
                if (d != dprev) {
                    if (dprev >= 0 && m > -CUDART_INF_F)
                        atomicMax(mkey + (size_t)dprev * 128 + ch * 64 + col, fenc(m));
                    m = -CUDART_INF_F;
                    dprev = d;
                }
                m = fmaxf(m, v);
            }
            if (dprev >= 0 && m > -CUDART_INF_F)
                atomicMax(mkey + (size_t)dprev * 128 + ch * 64 + col, fenc(m));
        }
    }
}

__global__ void k_ec_final(const float* __restrict__ a, const unsigned* __restrict__ mk,
                           float* __restrict__ h, int n)
{
    int idx = blockIdx.x * blockDim.x + threadIdx.x;
    if (idx < n * 128) {
        int i = idx >> 7;
        h[idx] = (g_deg[i] > 0) ? (a[idx] + fdec(mk[idx])) : 0.f;
    }
}

__global__ void k_final(const float* __restrict__ h, const float* __restrict__ Wfc,
                        const float* __restrict__ bfc, float* __restrict__ out, int n)
{
    int g = blockIdx.x * blockDim.x + threadIdx.x;
    int w = g >> 5, lane = g & 31;
    if (w >= n) return;
    float4 a = *(const float4*)&h[(size_t)w * 128 + lane * 4];
    float4 ww = *(const float4*)&Wfc[lane * 4];
    float s = a.x * ww.x + a.y * ww.y + a.z * ww.z + a.w * ww.w;
#pragma unroll
    for (int o = 16; o > 0; o >>= 1) s += __shfl_xor_sync(0xffffffffu, s, o);
    if (lane == 0) out[w] = s + bfc[0];
}

// ---------------- launch -----------------------------------------------------
extern "C" void kernel_launch(void* const* d_in, const int* in_sizes, int n_in,
                              void* d_out, int out_size)
{
    const float* x   = (const float*)d_in[0];
    const int*   ei  = (const int*)d_in[1];
    const float* Wm  = (const float*)d_in[2];
    const float* bm  = (const float*)d_in[3];
    const float* Wc  = (const float*)d_in[4];
    const float* bc  = (const float*)d_in[5];
    const float* Wg1 = (const float*)d_in[6];
    const float* bg1 = (const float*)d_in[7];
    const float* Wg2 = (const float*)d_in[8];
    const float* bg2 = (const float*)d_in[9];
    const float* Wg3 = (const float*)d_in[10];
    const float* bg3 = (const float*)d_in[11];
    const float* e1g = (const float*)d_in[12];
    const float* e1b = (const float*)d_in[13];
    const float* e1m = (const float*)d_in[14];
    const float* e1v = (const float*)d_in[15];
    const float* e1W = (const float*)d_in[16];
    const float* e2g = (const float*)d_in[17];
    const float* e2b = (const float*)d_in[18];
    const float* e2m = (const float*)d_in[19];
    const float* e2v = (const float*)d_in[20];
    const float* e2W = (const float*)d_in[21];
    const float* e3g = (const float*)d_in[22];
    const float* e3b = (const float*)d_in[23];
    const float* e3m = (const float*)d_in[24];
    const float* e3v = (const float*)d_in[25];
    const float* e3W = (const float*)d_in[26];
    const float* Wfc = (const float*)d_in[27];
    const float* bfc = (const float*)d_in[28];
    float* out = (float*)d_out;

    const int n = in_sizes[0] / 512;
    const int E = in_sizes[1] / 2;
    const int* src = ei;
    const int* dst = ei + E;

    float *p_x0, *p_tmp, *p_bufA, *p_bufB, *p_nt;
    float *p_scl, *p_shl, *p_sct, *p_sht;
    unsigned* p_mkey;
    int* p_deg;
    uint32_t *we1h, *we1l, *we2h, *we2l, *we3h, *we3l;
    uint32_t *wn1h, *wn1l, *wn2h, *wn2l, *wn3h, *wn3l;
    uint32_t *wmh, *wml, *wch, *wcl;
    uint32_t *wg1h, *wg1l, *wg2h, *wg2l, *wg3h, *wg3l;
    cudaGetSymbolAddress((void**)&p_x0, g_x0);
    cudaGetSymbolAddress((void**)&p_tmp, g_tmp);
    cudaGetSymbolAddress((void**)&p_bufA, g_bufA);
    cudaGetSymbolAddress((void**)&p_bufB, g_bufB);
    cudaGetSymbolAddress((void**)&p_nt, g_nt);
    cudaGetSymbolAddress((void**)&p_mkey, g_mkey);
    cudaGetSymbolAddress((void**)&p_deg, g_deg);
    cudaGetSymbolAddress((void**)&p_scl, g_scl);
    cudaGetSymbolAddress((void**)&p_shl, g_shl);
    cudaGetSymbolAddress((void**)&p_sct, g_sct);
    cudaGetSymbolAddress((void**)&p_sht, g_sht);
    cudaGetSymbolAddress((void**)&we1h, g_we1h); cudaGetSymbolAddress((void**)&we1l, g_we1l);
    cudaGetSymbolAddress((void**)&we2h, g_we2h); cudaGetSymbolAddress((void**)&we2l, g_we2l);
    cudaGetSymbolAddress((void**)&we3h, g_we3h); cudaGetSymbolAddress((void**)&we3l, g_we3l);
    cudaGetSymbolAddress((void**)&wn1h, g_wn1h); cudaGetSymbolAddress((void**)&wn1l, g_wn1l);
    cudaGetSymbolAddress((void**)&wn2h, g_wn2h); cudaGetSymbolAddress((void**)&wn2l, g_wn2l);
    cudaGetSymbolAddress((void**)&wn3h, g_wn3h); cudaGetSymbolAddress((void**)&wn3l, g_wn3l);
    cudaGetSymbolAddress((void**)&wmh, g_wmh);   cudaGetSymbolAddress((void**)&wml, g_wml);
    cudaGetSymbolAddress((void**)&wch, g_wch);   cudaGetSymbolAddress((void**)&wcl, g_wcl);
    cudaGetSymbolAddress((void**)&wg1h, g_wg1h); cudaGetSymbolAddress((void**)&wg1l, g_wg1l);
    cudaGetSymbolAddress((void**)&wg2h, g_wg2h); cudaGetSymbolAddress((void**)&wg2l, g_wg2l);
    cudaGetSymbolAddress((void**)&wg3h, g_wg3h); cudaGetSymbolAddress((void**)&wg3l, g_wg3l);

    const int THR = 256;
    auto blks = [&](int work) { return (work + THR - 1) / THR; };
    const int mb = (n + 127) / 128;
    const int eb = (E + 127) / 128;
    const int wb = (E + 63) / 64;   // blocks for 8-edges-per-warp kernels

    // ---- weight prep ----
    k_pack<<<blks(128 * 128), THR>>>(e1W + 256 * 128, 256, 128, we1h, we1l);
    k_pack<<<blks(64 * 128), THR>>>(e2W + 128 * 128, 128, 128, we2h, we2l);
    k_pack<<<blks(64 * 128), THR>>>(e3W + 128 * 128, 128, 128, we3h, we3l);
    k_pack<<<blks(128 * 128), THR>>>(e1W, 256, 128, wn1h, wn1l);
    k_pack<<<blks(64 * 128), THR>>>(e2W, 128, 128, wn2h, wn2l);
    k_pack<<<blks(64 * 128), THR>>>(e3W, 128, 128, wn3h, wn3l);
    k_pack<<<blks(256 * 64), THR>>>(Wm, 512, 64, wmh, wml);
    k_pack<<<blks(256 * 64), THR>>>(Wc, 512, 64, wch, wcl);
    k_pack<<<blks(32 * 128), THR>>>(Wg1, 64, 128, wg1h, wg1l);
    k_pack<<<blks(64 * 128), THR>>>(Wg2, 128, 128, wg2h, wg2l);
    k_pack<<<blks(64 * 256), THR>>>(Wg3, 128, 256, wg3h, wg3l);
    k_bn<<<1, 256>>>(e1g + 256, e1b + 256, e1m + 256, e1v + 256, 256, p_scl, p_shl);
    k_bn<<<1, 128>>>(e2g + 128, e2b + 128, e2m + 128, e2v + 128, 128, p_scl + 256, p_shl + 256);
    k_bn<<<1, 128>>>(e3g + 128, e3b + 128, e3m + 128, e3v + 128, 128, p_scl + 384, p_shl + 384);
    k_bn<<<1, 256>>>(e1g, e1b, e1m, e1v, 256, p_sct, p_sht);
    k_bn<<<1, 128>>>(e2g, e2b, e2m, e2v, 128, p_sct + 256, p_sht + 256);
    k_bn<<<1, 128>>>(e3g, e3b, e3m, e3v, 128, p_sct + 384, p_sht + 384);

    // ---- degrees + normalization + dst-sort ----
    k_zero_i32<<<blks(n), THR>>>(p_deg, n);
    k_count_deg<<<blks(E), THR>>>(dst, E);
    k_dinv<<<blks(n), THR>>>(n);
    k_scan<<<1, 256>>>(n);
    k_scatter<<<blks(E), THR>>>(src, dst, E);

    // ---- input projection ----
    k_mm<64, 0, 1><<<dim3(mb, 1), THR>>>(x, wmh, wml, p_x0, n, 512, 64, nullptr, nullptr, bm);
    k_mm<64, 0, 2><<<dim3(mb, 1), THR>>>(x, wch, wcl, p_x0, n, 512, 64, nullptr, nullptr, bc);

    // ---- GCN (aggregate-first) ----
    k_gcn_init<<<blks(n * 64), THR>>>(p_x0, p_tmp, n, 64);
    k_gcn_edge2<<<wb, THR>>>(p_x0, p_tmp, E, 16);
    k_mm<128, 0, 0><<<dim3(mb, 1), THR>>>(p_tmp, wg1h, wg1l, p_bufA, n, 64, 128,
                                          nullptr, nullptr, bg1);

    k_gcn_init<<<blks(n * 128), THR>>>(p_bufA, p_tmp, n, 128);
    k_gcn_edge2<<<wb, THR>>>(p_bufA, p_tmp, E, 32);
    k_mm<128, 0, 0><<<dim3(mb, 1), THR>>>(p_tmp, wg2h, wg2l, p_bufB, n, 128, 128,
                                          nullptr, nullptr, bg2);

    k_gcn_init<<<blks(n * 128), THR>>>(p_bufB, p_tmp, n, 128);
    k_gcn_edge2<<<wb, THR>>>(p_bufB, p_tmp, E, 32);
    k_mm<128, 0, 0><<<dim3(mb, 2), THR>>>(p_tmp, wg3h, wg3l, p_bufA, n, 128, 256,
                                          nullptr, nullptr, bg3);

    // ---- EdgeConv 1: C=256 (in bufA -> out bufB) ----
    k_mm<128, 1, 0><<<dim3(mb, 1), THR>>>(p_bufA, wn1h, wn1l, p_nt, n, 256, 128,
                                          p_sct, p_sht, nullptr);
    k_zero_u32<<<blks(n * 128), THR>>>(p_mkey, n * 128);
    k_ec_mma<256><<<eb, THR>>>(p_bufA, we1h, we1l, p_scl, p_shl, p_mkey, E);
    k_ec_final<<<blks(n * 128), THR>>>(p_nt, p_mkey, p_bufB, n);

    // ---- EdgeConv 2: C=128 (in bufB -> out tmp) ----
    k_mm<128, 1, 0><<<dim3(mb, 1), THR>>>(p_bufB, wn2h, wn2l, p_nt, n, 128, 128,
                                          p_sct + 256, p_sht + 256, nullptr);
    k_zero_u32<<<blks(n * 128), THR>>>(p_mkey, n * 128);
    k_ec_mma<128><<<eb, THR>>>(p_bufB, we2h, we2l, p_scl + 256, p_shl + 256, p_mkey, E);
    k_ec_final<<<blks(n * 128), THR>>>(p_nt, p_mkey, p_tmp, n);

    // ---- EdgeConv 3: C=128 (in tmp -> out bufA) ----
    k_mm<128, 1, 0><<<dim3(mb, 1), THR>>>(p_tmp, wn3h, wn3l, p_nt, n, 128, 128,
                                          p_sct + 384, p_sht + 384, nullptr);
    k_zero_u32<<<blks(n * 128), THR>>>(p_mkey, n * 128);
    k_ec_mma<128><<<eb, THR>>>(p_tmp, we3h, we3l, p_scl + 384, p_shl + 384, p_mkey, E);
    k_ec_final<<<blks(n * 128), THR>>>(p_nt, p_mkey, p_bufA, n);

    // ---- final FC ----
    k_final<<<blks(n * 32), THR>>>(p_bufA, Wfc, bfc, out, n);
}